// round 1
// baseline (speedup 1.0000x reference)
#include <cuda_runtime.h>
#include <cuda_bf16.h>
#include <math.h>

#define BB 4
#define TT 1024
#define CC 1024
#define HH 16
#define DD 64
#define EE 8
#define HID 128

#define NEG_HUGE (-3.38953139e38f)

// Scratch (allocation-free rule: __device__ globals)
__device__ float g_q[BB*HH*TT*DD];   // [B,H,T,D]
__device__ float g_k[BB*HH*TT*DD];
__device__ float g_v[BB*HH*TT*DD];
__device__ float g_ao[BB*TT*CC];     // attention output, [B,T,C] with c = h*64+d

__device__ __forceinline__ float gelu_tanh(float t) {
    float t3 = t * t * t;
    return 0.5f * t * (1.0f + tanhf(0.7978845608028654f * (t + 0.044715f * t3)));
}

// ---------------------------------------------------------------------------
// Kernel 1: per-(b,t,h) MoE projections for q,k,v + fused RoPE on q,k.
// 96 threads: warp 0 -> q, warp 1 -> k, warp 2 -> v.
// ---------------------------------------------------------------------------
__global__ void __launch_bounds__(96) moe_qkv_kernel(
    const float* __restrict__ x, const int* __restrict__ pos_ids,
    const float* __restrict__ cosT, const float* __restrict__ sinT,
    const float* __restrict__ rq, const float* __restrict__ rk, const float* __restrict__ rv,
    const float* __restrict__ qw1, const float* __restrict__ qw2,
    const float* __restrict__ kw1, const float* __restrict__ kw2,
    const float* __restrict__ vw1, const float* __restrict__ vw2)
{
    const int h = blockIdx.x;
    const int t = blockIdx.y;
    const int b = blockIdx.z;
    const int tid  = threadIdx.x;
    const int w    = tid >> 5;
    const int lane = tid & 31;

    __shared__ float xs[DD];
    __shared__ float hs[3][HID];

    if (tid < DD) xs[tid] = x[((size_t)(b * TT) + t) * CC + h * DD + tid];
    __syncthreads();

    const float* r  = (w == 0) ? rq  : (w == 1) ? rk  : rv;
    const float* w1 = (w == 0) ? qw1 : (w == 1) ? kw1 : vw1;
    const float* w2 = (w == 0) ? qw2 : (w == 1) ? kw2 : vw2;
    float* outg     = (w == 0) ? g_q : (w == 1) ? g_k : g_v;

    // ---- router logits (lanes 0..7 each own one expert) ----
    float acc = 0.0f;
    if (lane < EE) {
        #pragma unroll 16
        for (int d = 0; d < DD; d++) acc += xs[d] * r[d * EE + lane];
    }
    // top-2 + softmax, replicated across all lanes
    float m1 = NEG_HUGE, m2 = NEG_HUGE;
    int   i1 = 0, i2 = 0;
    #pragma unroll
    for (int e = 0; e < EE; e++) {
        float v = __shfl_sync(0xffffffffu, acc, e);
        if (v > m1)       { m2 = m1; i2 = i1; m1 = v; i1 = e; }
        else if (v > m2)  { m2 = v;  i2 = e; }
    }
    float dex = expf(m2 - m1);
    float wt1 = 1.0f / (1.0f + dex);
    float wt2 = dex * wt1;

    // ---- two experts ----
    float2 o2 = make_float2(0.0f, 0.0f);
    #pragma unroll
    for (int kk = 0; kk < 2; kk++) {
        const int   e  = kk ? i2 : i1;
        const float wt = kk ? wt2 : wt1;

        // hidden = gelu(x @ w1[e]) : lane owns hidden units 4*lane..4*lane+3
        float4 ha = make_float4(0.f, 0.f, 0.f, 0.f);
        const float4* w1p = (const float4*)(w1 + (size_t)e * DD * HID) + lane;
        #pragma unroll 8
        for (int d = 0; d < DD; d++) {
            float4 wv = w1p[d * (HID / 4)];
            float  xd = xs[d];
            ha.x += xd * wv.x; ha.y += xd * wv.y;
            ha.z += xd * wv.z; ha.w += xd * wv.w;
        }
        hs[w][4 * lane + 0] = gelu_tanh(ha.x);
        hs[w][4 * lane + 1] = gelu_tanh(ha.y);
        hs[w][4 * lane + 2] = gelu_tanh(ha.z);
        hs[w][4 * lane + 3] = gelu_tanh(ha.w);
        __syncwarp();

        // out = hidden @ w2[e] : lane owns outputs 2*lane, 2*lane+1
        float2 oa = make_float2(0.f, 0.f);
        const float2* w2p = (const float2*)(w2 + (size_t)e * HID * DD) + lane;
        #pragma unroll 8
        for (int j = 0; j < HID; j++) {
            float2 wv = w2p[j * (DD / 2)];
            float  hj = hs[w][j];
            oa.x += hj * wv.x; oa.y += hj * wv.y;
        }
        o2.x += wt * oa.x;
        o2.y += wt * oa.y;
        __syncwarp();   // before hs is overwritten by the next expert
    }

    // ---- RoPE on q,k (lane owns dims g0=2*lane, g0+1; pair lane is lane^16) ----
    const int g0 = 2 * lane;
    if (w < 2) {
        int p = pos_ids[b * TT + t];
        float rx = __shfl_xor_sync(0xffffffffu, o2.x, 16);
        float ry = __shfl_xor_sync(0xffffffffu, o2.y, 16);
        float rot0 = (lane < 16) ? -rx : rx;
        float rot1 = (lane < 16) ? -ry : ry;
        float c0 = cosT[p * DD + g0],     c1 = cosT[p * DD + g0 + 1];
        float s0 = sinT[p * DD + g0],     s1 = sinT[p * DD + g0 + 1];
        o2.x = o2.x * c0 + rot0 * s0;
        o2.y = o2.y * c1 + rot1 * s1;
    }
    size_t out_base = (((size_t)b * HH + h) * TT + t) * DD;
    *(float2*)&outg[out_base + g0] = o2;
}

// ---------------------------------------------------------------------------
// Kernel 2: causal flash attention, fp32. BQ=BK=64, 512 threads (16 warps),
// each warp owns 4 query rows. K tile stored d-major with XOR swizzle.
// ---------------------------------------------------------------------------
__global__ void __launch_bounds__(512) attn_kernel()
{
    const int qt  = blockIdx.x;     // 0..15
    const int bh  = blockIdx.y;     // 0..63
    const int tid = threadIdx.x;
    const int w    = tid >> 5;
    const int lane = tid & 31;

    __shared__ float qs[64 * 64];
    __shared__ float ks[64 * 64];   // ks[d*64 + (j ^ (d&31))]
    __shared__ float vs[64 * 64];   // vs[j*64 + d]

    const float* qg = g_q + (size_t)bh * TT * DD;
    const float* kg = g_k + (size_t)bh * TT * DD;
    const float* vg = g_v + (size_t)bh * TT * DD;
    const int q0 = qt * 64;

    for (int idx = tid; idx < 4096; idx += 512)
        qs[idx] = qg[(size_t)q0 * 64 + idx] * 0.125f;   // pre-scale by 1/sqrt(D)

    const int rbase = w * 4;
    float m[4], l[4], o0[4], o1[4];
    #pragma unroll
    for (int r = 0; r < 4; r++) { m[r] = NEG_HUGE; l[r] = 0.f; o0[r] = 0.f; o1[r] = 0.f; }

    for (int kt = 0; kt <= qt; kt++) {
        const int k0 = kt * 64;
        __syncthreads();
        for (int idx = tid; idx < 4096; idx += 512) {
            int j = idx >> 6, d = idx & 63;
            ks[d * 64 + (j ^ (d & 31))] = kg[(size_t)(k0 + j) * 64 + d];
            vs[idx]                     = vg[(size_t)(k0 + j) * 64 + d];
        }
        __syncthreads();

        float s0[4] = {0.f, 0.f, 0.f, 0.f};
        float s1[4] = {0.f, 0.f, 0.f, 0.f};
        #pragma unroll 16
        for (int d = 0; d < 64; d++) {
            int   c   = d & 31;
            float kv0 = ks[d * 64 + (lane ^ c)];
            float kv1 = ks[d * 64 + (lane ^ c) + 32];
            #pragma unroll
            for (int r = 0; r < 4; r++) {
                float qd = qs[(rbase + r) * 64 + d];
                s0[r] += qd * kv0;
                s1[r] += qd * kv1;
            }
        }

        if (kt == qt) {
            #pragma unroll
            for (int r = 0; r < 4; r++) {
                int grow = rbase + r;                 // q0==k0 on the diagonal tile
                if (lane      > grow) s0[r] = NEG_HUGE;
                if (lane + 32 > grow) s1[r] = NEG_HUGE;
            }
        }

        #pragma unroll
        for (int r = 0; r < 4; r++) {
            float mt = fmaxf(s0[r], s1[r]);
            #pragma unroll
            for (int off = 16; off; off >>= 1)
                mt = fmaxf(mt, __shfl_xor_sync(0xffffffffu, mt, off));
            float mn    = fmaxf(m[r], mt);
            float alpha = __expf(m[r] - mn);
            float p0 = __expf(s0[r] - mn);
            float p1 = __expf(s1[r] - mn);
            float ps = p0 + p1;
            #pragma unroll
            for (int off = 16; off; off >>= 1)
                ps += __shfl_xor_sync(0xffffffffu, ps, off);
            l[r] = l[r] * alpha + ps;
            m[r] = mn;
            o0[r] *= alpha; o1[r] *= alpha;
            s0[r] = p0;     s1[r] = p1;     // reuse as p
        }

        #pragma unroll 8
        for (int j = 0; j < 32; j++) {
            float v0 = vs[j * 64 + lane];
            float v1 = vs[j * 64 + lane + 32];
            #pragma unroll
            for (int r = 0; r < 4; r++) {
                float pj = __shfl_sync(0xffffffffu, s0[r], j);
                o0[r] += pj * v0;
                o1[r] += pj * v1;
            }
        }
        #pragma unroll 8
        for (int j = 0; j < 32; j++) {
            float v0 = vs[(j + 32) * 64 + lane];
            float v1 = vs[(j + 32) * 64 + lane + 32];
            #pragma unroll
            for (int r = 0; r < 4; r++) {
                float pj = __shfl_sync(0xffffffffu, s1[r], j);
                o0[r] += pj * v0;
                o1[r] += pj * v1;
            }
        }
    }

    const int b = bh / HH, h = bh % HH;
    #pragma unroll
    for (int r = 0; r < 4; r++) {
        float inv = 1.0f / l[r];
        int   row = q0 + rbase + r;
        float* dst = g_ao + ((size_t)(b * TT) + row) * CC + h * DD;
        dst[lane]      = o0[r] * inv;
        dst[lane + 32] = o1[r] * inv;
    }
}

// ---------------------------------------------------------------------------
// Kernel 3: y = ao @ o_w^T.  M=4096, N=1024, K=1024.
// 64x64 tiles, BK=16, 256 threads, 4x4 register tile per thread.
// ---------------------------------------------------------------------------
__global__ void __launch_bounds__(256) outproj_kernel(
    const float* __restrict__ ow, float* __restrict__ y)
{
    __shared__ __align__(16) float As[16][64];
    __shared__ __align__(16) float Bs[16][64];

    const int tid = threadIdx.x;
    const int n0 = blockIdx.x * 64;
    const int m0 = blockIdx.y * 64;
    const int tx = tid & 15, ty = tid >> 4;
    const int lr = tid >> 2;          // 0..63: row within tile
    const int lc = (tid & 3) * 4;     // 0,4,8,12: k offset

    float acc[4][4];
    #pragma unroll
    for (int i = 0; i < 4; i++)
        #pragma unroll
        for (int j = 0; j < 4; j++) acc[i][j] = 0.f;

    for (int k0 = 0; k0 < 1024; k0 += 16) {
        float4 a  = *(const float4*)&g_ao[(size_t)(m0 + lr) * 1024 + k0 + lc];
        float4 bv = *(const float4*)&ow  [(size_t)(n0 + lr) * 1024 + k0 + lc];
        As[lc + 0][lr] = a.x;  As[lc + 1][lr] = a.y;
        As[lc + 2][lr] = a.z;  As[lc + 3][lr] = a.w;
        Bs[lc + 0][lr] = bv.x; Bs[lc + 1][lr] = bv.y;
        Bs[lc + 2][lr] = bv.z; Bs[lc + 3][lr] = bv.w;
        __syncthreads();

        #pragma unroll
        for (int kk = 0; kk < 16; kk++) {
            float4 av = *(const float4*)&As[kk][ty * 4];
            float4 bw = *(const float4*)&Bs[kk][tx * 4];
            acc[0][0] += av.x * bw.x; acc[0][1] += av.x * bw.y;
            acc[0][2] += av.x * bw.z; acc[0][3] += av.x * bw.w;
            acc[1][0] += av.y * bw.x; acc[1][1] += av.y * bw.y;
            acc[1][2] += av.y * bw.z; acc[1][3] += av.y * bw.w;
            acc[2][0] += av.z * bw.x; acc[2][1] += av.z * bw.y;
            acc[2][2] += av.z * bw.z; acc[2][3] += av.z * bw.w;
            acc[3][0] += av.w * bw.x; acc[3][1] += av.w * bw.y;
            acc[3][2] += av.w * bw.z; acc[3][3] += av.w * bw.w;
        }
        __syncthreads();
    }

    #pragma unroll
    for (int i = 0; i < 4; i++) {
        float4 v = make_float4(acc[i][0], acc[i][1], acc[i][2], acc[i][3]);
        *(float4*)&y[(size_t)(m0 + ty * 4 + i) * 1024 + n0 + tx * 4] = v;
    }
}

// ---------------------------------------------------------------------------
extern "C" void kernel_launch(void* const* d_in, const int* in_sizes, int n_in,
                              void* d_out, int out_size)
{
    const float* x    = (const float*)d_in[0];
    const int*   pid  = (const int*)  d_in[1];
    const float* cosT = (const float*)d_in[2];
    const float* sinT = (const float*)d_in[3];
    const float* rq   = (const float*)d_in[4];
    const float* rk   = (const float*)d_in[5];
    const float* rv   = (const float*)d_in[6];
    const float* qw1  = (const float*)d_in[7];
    const float* qw2  = (const float*)d_in[8];
    const float* kw1  = (const float*)d_in[9];
    const float* kw2  = (const float*)d_in[10];
    const float* vw1  = (const float*)d_in[11];
    const float* vw2  = (const float*)d_in[12];
    const float* ow   = (const float*)d_in[13];
    float* y = (float*)d_out;

    dim3 g1(HH, TT, BB);
    moe_qkv_kernel<<<g1, 96>>>(x, pid, cosT, sinT, rq, rk, rv,
                               qw1, qw2, kw1, kw2, vw1, vw2);

    dim3 g2(TT / 64, BB * HH);
    attn_kernel<<<g2, 512>>>();

    dim3 g3(CC / 64, (BB * TT) / 64);
    outproj_kernel<<<g3, 256>>>(ow, y);
}

// round 2
// speedup vs baseline: 1.3029x; 1.3029x over previous
#include <cuda_runtime.h>
#include <cuda_bf16.h>
#include <math.h>

#define BB 4
#define TT 1024
#define CC 1024
#define HH 16
#define DD 64
#define EE 8
#define HID 128
#define NTOK (BB*TT)          // 4096 global tokens
#define NUNIT (3*HH*EE)       // 384 (proj, head, expert) units
#define SPLITS 4

#define NEG_HUGE (-3.38953139e38f)

typedef unsigned long long ull;

// ---------------- f32x2 packed-math helpers (B300 FFMA2) ----------------
__device__ __forceinline__ ull pack2(float lo, float hi) {
    ull r; asm("mov.b64 %0, {%1,%2};" : "=l"(r) : "f"(lo), "f"(hi)); return r;
}
__device__ __forceinline__ void fma2(ull& d, ull a, ull b) {
    asm("fma.rn.f32x2 %0, %1, %2, %0;" : "+l"(d) : "l"(a), "l"(b));
}
__device__ __forceinline__ float2 unpack2(ull v) {
    float2 f; asm("mov.b64 {%0,%1}, %2;" : "=f"(f.x), "=f"(f.y) : "l"(v)); return f;
}

// ---------------- device scratch (allocation-free rule) ----------------
__device__ float g_q[BB*HH*TT*DD];   // [B,H,T,D], post-RoPE
__device__ float g_k[BB*HH*TT*DD];
__device__ float g_v[BB*HH*TT*DD];
__device__ float g_ao[BB*TT*CC];     // attention output [B,T,C], c = h*64+d
__device__ unsigned int g_cnt[NUNIT];                     // tokens per unit
__device__ unsigned int g_ent_id[NUNIT*NTOK];             // tk | slot<<31
__device__ float        g_ent_wt[NUNIT*NTOK];             // routing weight
__device__ float g_part[2ll*3*HH*NTOK*DD];                // [slot][proj][h][tk][d]

__device__ __forceinline__ float gelu_tanh(float t) {
    float t3 = t * t * t;
    return 0.5f * t * (1.0f + tanhf(0.7978845608028654f * (t + 0.044715f * t3)));
}

// ---------------------------------------------------------------------------
// Kernel 0: zero the routing counters
// ---------------------------------------------------------------------------
__global__ void zero_cnt_kernel() {
    if (threadIdx.x < NUNIT) g_cnt[threadIdx.x] = 0u;
}

// ---------------------------------------------------------------------------
// Kernel 1: routing. One block per global token (b*T+t), 96 threads:
// warp w = projection (q,k,v). Appends (token, weight, slot) to expert lists.
// ---------------------------------------------------------------------------
__global__ void __launch_bounds__(96) route_kernel(
    const float* __restrict__ x,
    const float* __restrict__ rq, const float* __restrict__ rk,
    const float* __restrict__ rv)
{
    const int tk   = blockIdx.x;             // 0..4095
    const int tid  = threadIdx.x;
    const int w    = tid >> 5;
    const int lane = tid & 31;

    __shared__ float xs[CC];
    __shared__ float rs[3][DD*EE];

    for (int i = tid; i < CC/4; i += 96)
        ((float4*)xs)[i] = ((const float4*)(x + (size_t)tk * CC))[i];
    for (int i = tid; i < DD*EE; i += 96) {
        rs[0][i] = rq[i]; rs[1][i] = rk[i]; rs[2][i] = rv[i];
    }
    __syncthreads();

    for (int h = 0; h < HH; h++) {
        float acc = 0.0f;
        if (lane < EE) {
            #pragma unroll 16
            for (int d = 0; d < DD; d++) acc += xs[h*DD + d] * rs[w][d*EE + lane];
        }
        float m1 = NEG_HUGE, m2 = NEG_HUGE;
        int   i1 = 0, i2 = 0;
        #pragma unroll
        for (int e = 0; e < EE; e++) {
            float v = __shfl_sync(0xffffffffu, acc, e);
            if (v > m1)      { m2 = m1; i2 = i1; m1 = v; i1 = e; }
            else if (v > m2) { m2 = v;  i2 = e; }
        }
        if (lane == 0) {
            float dex = expf(m2 - m1);
            float wt1 = 1.0f / (1.0f + dex);
            float wt2 = dex * wt1;
            int base = (w * HH + h) * EE;
            unsigned int p1 = atomicAdd(&g_cnt[base + i1], 1u);
            g_ent_id[(size_t)(base + i1) * NTOK + p1] = (unsigned int)tk;
            g_ent_wt[(size_t)(base + i1) * NTOK + p1] = wt1;
            unsigned int p2 = atomicAdd(&g_cnt[base + i2], 1u);
            g_ent_id[(size_t)(base + i2) * NTOK + p2] = (unsigned int)tk | 0x80000000u;
            g_ent_wt[(size_t)(base + i2) * NTOK + p2] = wt2;
        }
    }
}

// ---------------------------------------------------------------------------
// Kernel 2: expert-grouped MoE GEMM. One block per (unit, split).
// Weights in SMEM (64KB), 64-token tiles, f32x2 packed FMA.
// Dynamic smem: w1s[64*128] + w2s[128*64] + hs[64*128] + xs[64*64] = 114688 B.
// ---------------------------------------------------------------------------
__global__ void __launch_bounds__(256) moe_gemm_kernel(
    const float* __restrict__ x,
    const float* __restrict__ qw1, const float* __restrict__ qw2,
    const float* __restrict__ kw1, const float* __restrict__ kw2,
    const float* __restrict__ vw1, const float* __restrict__ vw2)
{
    const int gid  = blockIdx.x;
    const int unit = gid / SPLITS;
    const int s    = gid % SPLITS;
    const int proj = unit >> 7;           // /128
    const int h    = (unit >> 3) & 15;
    const int e    = unit & 7;

    const float* w1 = ((proj == 0) ? qw1 : (proj == 1) ? kw1 : vw1) + (size_t)e * DD * HID;
    const float* w2 = ((proj == 0) ? qw2 : (proj == 1) ? kw2 : vw2) + (size_t)e * HID * DD;

    extern __shared__ float sm[];
    float* w1s = sm;            // [64][128]
    float* w2s = sm + 8192;     // [128][64]
    float* hs  = sm + 16384;    // [64][128]
    float* xs  = sm + 24576;    // [64][64]
    __shared__ unsigned int stk[64];
    __shared__ float        swt[64];

    const int tid = threadIdx.x;
    const int ty  = tid >> 4;   // 0..15 -> token group of 4
    const int tx  = tid & 15;   // 0..15 -> column lanes

    for (int i = tid; i < 2048; i += 256) {
        ((float4*)w1s)[i] = ((const float4*)w1)[i];
        ((float4*)w2s)[i] = ((const float4*)w2)[i];
    }
    const int nt = (int)g_cnt[unit];
    const size_t ent_base = (size_t)unit * NTOK;

    for (int tile = s; tile * 64 < nt; tile += SPLITS) {
        const int base = tile * 64;
        __syncthreads();
        if (tid < 64) {
            int idx = base + tid;
            if (idx < nt) {
                stk[tid] = g_ent_id[ent_base + idx];
                swt[tid] = g_ent_wt[ent_base + idx];
            } else {
                stk[tid] = 0xFFFFFFFFu;
                swt[tid] = 0.0f;
            }
        }
        __syncthreads();
        {   // gather x rows: 4 threads per token, 4 float4 each
            int tok = tid >> 2, part = tid & 3;
            unsigned int id = stk[tok];
            if (id != 0xFFFFFFFFu) {
                unsigned int tkk = id & 0x7FFFFFFFu;
                const float4* src = (const float4*)(x + (size_t)tkk * CC + h * DD);
                float4* dst = (float4*)(xs + tok * DD);
                #pragma unroll
                for (int q = 0; q < 4; q++) dst[part*4 + q] = src[part*4 + q];
            }
        }
        __syncthreads();

        // ---- stage 1: hs = gelu(xs @ w1)  (tokens ty*4..+3, hid 2tx + 32p) ----
        ull acc[4][4];
        #pragma unroll
        for (int r = 0; r < 4; r++)
            #pragma unroll
            for (int p = 0; p < 4; p++) acc[r][p] = 0ull;

        #pragma unroll 8
        for (int d = 0; d < 64; d++) {
            ull wv[4];
            #pragma unroll
            for (int p = 0; p < 4; p++)
                wv[p] = *(const ull*)&w1s[d*HID + 2*tx + 32*p];
            #pragma unroll
            for (int r = 0; r < 4; r++) {
                float xv = xs[(ty*4 + r)*DD + d];
                ull xp = pack2(xv, xv);
                #pragma unroll
                for (int p = 0; p < 4; p++) fma2(acc[r][p], xp, wv[p]);
            }
        }
        #pragma unroll
        for (int r = 0; r < 4; r++)
            #pragma unroll
            for (int p = 0; p < 4; p++) {
                float2 v = unpack2(acc[r][p]);
                hs[(ty*4 + r)*HID + 2*tx + 32*p]     = gelu_tanh(v.x);
                hs[(ty*4 + r)*HID + 2*tx + 32*p + 1] = gelu_tanh(v.y);
            }
        __syncthreads();

        // ---- stage 2: out = hs @ w2  (tokens ty*4..+3, dims 2tx + 32c) ----
        ull oc[4][2];
        #pragma unroll
        for (int r = 0; r < 4; r++) { oc[r][0] = 0ull; oc[r][1] = 0ull; }

        #pragma unroll 8
        for (int j = 0; j < HID; j++) {
            ull wp0 = *(const ull*)&w2s[j*DD + 2*tx];
            ull wp1 = *(const ull*)&w2s[j*DD + 2*tx + 32];
            #pragma unroll
            for (int r = 0; r < 4; r++) {
                float hv = hs[(ty*4 + r)*HID + j];
                ull hp = pack2(hv, hv);
                fma2(oc[r][0], hp, wp0);
                fma2(oc[r][1], hp, wp1);
            }
        }
        #pragma unroll
        for (int r = 0; r < 4; r++) {
            int tok = ty*4 + r;
            unsigned int id = stk[tok];
            if (id == 0xFFFFFFFFu) continue;
            unsigned int slot = id >> 31;
            unsigned int tkk  = id & 0x7FFFFFFFu;
            float wt = swt[tok];
            float* dst = g_part + ((((size_t)slot*3 + proj)*HH + h)*NTOK + tkk)*DD;
            float2 v0 = unpack2(oc[r][0]);
            float2 v1 = unpack2(oc[r][1]);
            *(float2*)&dst[2*tx]      = make_float2(wt*v0.x, wt*v0.y);
            *(float2*)&dst[2*tx + 32] = make_float2(wt*v1.x, wt*v1.y);
        }
    }
}

// ---------------------------------------------------------------------------
// Kernel 3: combine both expert slots + RoPE (q,k) -> g_q/g_k/g_v [B,H,T,D]
// One warp per (proj,h,tk) row.
// ---------------------------------------------------------------------------
__global__ void __launch_bounds__(256) combine_rope_kernel(
    const int* __restrict__ pos_ids,
    const float* __restrict__ cosT, const float* __restrict__ sinT)
{
    const int gw   = blockIdx.x * 8 + (threadIdx.x >> 5);
    const int lane = threadIdx.x & 31;
    const int proj = gw / (HH * NTOK);
    const int rest = gw % (HH * NTOK);
    const int h  = rest / NTOK;
    const int tk = rest % NTOK;

    const size_t SLOT = (size_t)3 * HH * NTOK * DD;
    const size_t pbase = (((size_t)proj * HH + h) * NTOK + tk) * DD;
    float a0 = g_part[pbase + lane]      + g_part[pbase + SLOT + lane];
    float a1 = g_part[pbase + lane + 32] + g_part[pbase + SLOT + lane + 32];

    if (proj < 2) {
        int p = pos_ids[tk];
        float c0 = cosT[p*DD + lane],  c1 = cosT[p*DD + lane + 32];
        float s0 = sinT[p*DD + lane],  s1 = sinT[p*DD + lane + 32];
        float r0 = a0 * c0 - a1 * s0;
        float r1 = a1 * c1 + a0 * s1;
        a0 = r0; a1 = r1;
    }
    int b = tk >> 10, t = tk & 1023;
    float* outg = (proj == 0) ? g_q : (proj == 1) ? g_k : g_v;
    size_t obase = (((size_t)b * HH + h) * TT + t) * DD;
    outg[obase + lane]      = a0;
    outg[obase + lane + 32] = a1;
}

// ---------------------------------------------------------------------------
// Kernel 4: causal flash attention, fp32 + f32x2 QK. BQ=BK=64, 512 threads.
// ---------------------------------------------------------------------------
__global__ void __launch_bounds__(512) attn_kernel()
{
    const int qt  = blockIdx.x;     // 0..15
    const int bh  = blockIdx.y;     // 0..63
    const int tid = threadIdx.x;
    const int w    = tid >> 5;
    const int lane = tid & 31;

    __shared__ float qsT[64 * 66];  // transposed, padded: qsT[d*66 + row]
    __shared__ float ks[64 * 64];   // ks[d*64 + (j ^ (d&31))]
    __shared__ float vs[64 * 64];   // vs[j*64 + d]

    const float* qg = g_q + (size_t)bh * TT * DD;
    const float* kg = g_k + (size_t)bh * TT * DD;
    const float* vg = g_v + (size_t)bh * TT * DD;
    const int q0 = qt * 64;

    for (int idx = tid; idx < 4096; idx += 512) {
        int row = idx >> 6, d = idx & 63;
        qsT[d * 66 + row] = qg[(size_t)q0 * 64 + idx] * 0.125f;  // idx = row*64+d
    }

    const int rbase = w * 4;
    float m[4], l[4], o0[4], o1[4];
    #pragma unroll
    for (int r = 0; r < 4; r++) { m[r] = NEG_HUGE; l[r] = 0.f; o0[r] = 0.f; o1[r] = 0.f; }

    for (int kt = 0; kt <= qt; kt++) {
        const int k0 = kt * 64;
        __syncthreads();
        for (int idx = tid; idx < 4096; idx += 512) {
            int j = idx >> 6, d = idx & 63;
            ks[d * 64 + (j ^ (d & 31))] = kg[(size_t)(k0 + j) * 64 + d];
            vs[idx]                     = vg[(size_t)(k0 + j) * 64 + d];
        }
        __syncthreads();

        // QK: packed over row pairs; rp in {0,1} covers rows 2rp, 2rp+1
        ull s01[2][2];
        s01[0][0] = s01[0][1] = s01[1][0] = s01[1][1] = 0ull;
        #pragma unroll 8
        for (int d = 0; d < 64; d++) {
            int   c   = d & 31;
            float kv0 = ks[d * 64 + (lane ^ c)];
            float kv1 = ks[d * 64 + (lane ^ c) + 32];
            ull kp0 = pack2(kv0, kv0);
            ull kp1 = pack2(kv1, kv1);
            #pragma unroll
            for (int rp = 0; rp < 2; rp++) {
                ull qp = *(const ull*)&qsT[d * 66 + rbase + 2 * rp];
                fma2(s01[rp][0], qp, kp0);
                fma2(s01[rp][1], qp, kp1);
            }
        }
        float s0[4], s1[4];
        #pragma unroll
        for (int rp = 0; rp < 2; rp++) {
            float2 a = unpack2(s01[rp][0]);
            float2 b = unpack2(s01[rp][1]);
            s0[2*rp] = a.x; s0[2*rp+1] = a.y;
            s1[2*rp] = b.x; s1[2*rp+1] = b.y;
        }

        if (kt == qt) {
            #pragma unroll
            for (int r = 0; r < 4; r++) {
                int grow = rbase + r;
                if (lane      > grow) s0[r] = NEG_HUGE;
                if (lane + 32 > grow) s1[r] = NEG_HUGE;
            }
        }

        #pragma unroll
        for (int r = 0; r < 4; r++) {
            float mt = fmaxf(s0[r], s1[r]);
            #pragma unroll
            for (int off = 16; off; off >>= 1)
                mt = fmaxf(mt, __shfl_xor_sync(0xffffffffu, mt, off));
            float mn    = fmaxf(m[r], mt);
            float alpha = __expf(m[r] - mn);
            float p0 = __expf(s0[r] - mn);
            float p1 = __expf(s1[r] - mn);
            float ps = p0 + p1;
            #pragma unroll
            for (int off = 16; off; off >>= 1)
                ps += __shfl_xor_sync(0xffffffffu, ps, off);
            l[r] = l[r] * alpha + ps;
            m[r] = mn;
            o0[r] *= alpha; o1[r] *= alpha;
            s0[r] = p0;     s1[r] = p1;
        }

        #pragma unroll 8
        for (int j = 0; j < 32; j++) {
            float v0 = vs[j * 64 + lane];
            float v1 = vs[j * 64 + lane + 32];
            #pragma unroll
            for (int r = 0; r < 4; r++) {
                float pj = __shfl_sync(0xffffffffu, s0[r], j);
                o0[r] += pj * v0;
                o1[r] += pj * v1;
            }
        }
        #pragma unroll 8
        for (int j = 0; j < 32; j++) {
            float v0 = vs[(j + 32) * 64 + lane];
            float v1 = vs[(j + 32) * 64 + lane + 32];
            #pragma unroll
            for (int r = 0; r < 4; r++) {
                float pj = __shfl_sync(0xffffffffu, s1[r], j);
                o0[r] += pj * v0;
                o1[r] += pj * v1;
            }
        }
    }

    const int b = bh / HH, h = bh % HH;
    #pragma unroll
    for (int r = 0; r < 4; r++) {
        float inv = 1.0f / l[r];
        int   row = q0 + rbase + r;
        float* dst = g_ao + ((size_t)(b * TT) + row) * CC + h * DD;
        dst[lane]      = o0[r] * inv;
        dst[lane + 32] = o1[r] * inv;
    }
}

// ---------------------------------------------------------------------------
// Kernel 5: y = ao @ o_w^T, f32x2 packed.  M=4096, N=1024, K=1024.
// ---------------------------------------------------------------------------
__global__ void __launch_bounds__(256) outproj_kernel(
    const float* __restrict__ ow, float* __restrict__ y)
{
    __shared__ __align__(16) float As[16][64];
    __shared__ __align__(16) float Bs[16][64];

    const int tid = threadIdx.x;
    const int n0 = blockIdx.x * 64;
    const int m0 = blockIdx.y * 64;
    const int tx = tid & 15, ty = tid >> 4;
    const int lr = tid >> 2;
    const int lc = (tid & 3) * 4;

    ull acc2[4][2];
    #pragma unroll
    for (int i = 0; i < 4; i++) { acc2[i][0] = 0ull; acc2[i][1] = 0ull; }

    for (int k0 = 0; k0 < 1024; k0 += 16) {
        float4 a  = *(const float4*)&g_ao[(size_t)(m0 + lr) * 1024 + k0 + lc];
        float4 bv = *(const float4*)&ow  [(size_t)(n0 + lr) * 1024 + k0 + lc];
        As[lc + 0][lr] = a.x;  As[lc + 1][lr] = a.y;
        As[lc + 2][lr] = a.z;  As[lc + 3][lr] = a.w;
        Bs[lc + 0][lr] = bv.x; Bs[lc + 1][lr] = bv.y;
        Bs[lc + 2][lr] = bv.z; Bs[lc + 3][lr] = bv.w;
        __syncthreads();

        #pragma unroll
        for (int kk = 0; kk < 16; kk++) {
            float4 av = *(const float4*)&As[kk][ty * 4];
            float4 bw = *(const float4*)&Bs[kk][tx * 4];
            ull b0 = pack2(bw.x, bw.y);
            ull b1 = pack2(bw.z, bw.w);
            ull a0 = pack2(av.x, av.x);
            ull a1 = pack2(av.y, av.y);
            ull a2 = pack2(av.z, av.z);
            ull a3 = pack2(av.w, av.w);
            fma2(acc2[0][0], a0, b0); fma2(acc2[0][1], a0, b1);
            fma2(acc2[1][0], a1, b0); fma2(acc2[1][1], a1, b1);
            fma2(acc2[2][0], a2, b0); fma2(acc2[2][1], a2, b1);
            fma2(acc2[3][0], a3, b0); fma2(acc2[3][1], a3, b1);
        }
        __syncthreads();
    }

    #pragma unroll
    for (int i = 0; i < 4; i++) {
        float2 lo = unpack2(acc2[i][0]);
        float2 hi = unpack2(acc2[i][1]);
        *(float4*)&y[(size_t)(m0 + ty * 4 + i) * 1024 + n0 + tx * 4] =
            make_float4(lo.x, lo.y, hi.x, hi.y);
    }
}

// ---------------------------------------------------------------------------
extern "C" void kernel_launch(void* const* d_in, const int* in_sizes, int n_in,
                              void* d_out, int out_size)
{
    const float* x    = (const float*)d_in[0];
    const int*   pid  = (const int*)  d_in[1];
    const float* cosT = (const float*)d_in[2];
    const float* sinT = (const float*)d_in[3];
    const float* rq   = (const float*)d_in[4];
    const float* rk   = (const float*)d_in[5];
    const float* rv   = (const float*)d_in[6];
    const float* qw1  = (const float*)d_in[7];
    const float* qw2  = (const float*)d_in[8];
    const float* kw1  = (const float*)d_in[9];
    const float* kw2  = (const float*)d_in[10];
    const float* vw1  = (const float*)d_in[11];
    const float* vw2  = (const float*)d_in[12];
    const float* ow   = (const float*)d_in[13];
    float* y = (float*)d_out;

    static const int MOE_SMEM = (8192 + 8192 + 8192 + 4096) * 4;  // 114688 B
    cudaFuncSetAttribute(moe_gemm_kernel,
                         cudaFuncAttributeMaxDynamicSharedMemorySize, MOE_SMEM);

    zero_cnt_kernel<<<1, 512>>>();
    route_kernel<<<NTOK, 96>>>(x, rq, rk, rv);
    moe_gemm_kernel<<<NUNIT * SPLITS, 256, MOE_SMEM>>>(x, qw1, qw2, kw1, kw2, vw1, vw2);
    combine_rope_kernel<<<(3 * HH * NTOK) / 8, 256>>>(pid, cosT, sinT);

    dim3 g2(TT / 64, BB * HH);
    attn_kernel<<<g2, 512>>>();

    dim3 g3(CC / 64, (BB * TT) / 64);
    outproj_kernel<<<g3, 256>>>(ow, y);
}

// round 3
// speedup vs baseline: 1.7853x; 1.3703x over previous
#include <cuda_runtime.h>
#include <cuda_bf16.h>
#include <math.h>

#define BB 4
#define TT 1024
#define CC 1024
#define HH 16
#define DD 64
#define EE 8
#define HID 128
#define NTOK (BB*TT)          // 4096 global tokens
#define NUNIT (3*HH*EE)       // 384 (proj, head, expert) units
#define SPLITS 4

#define NEG_HUGE (-3.38953139e38f)

typedef unsigned long long ull;
typedef unsigned int uint;

// ---------------- f32x2 packed-math helpers (B300 FFMA2) ----------------
__device__ __forceinline__ ull pack2(float lo, float hi) {
    ull r; asm("mov.b64 %0, {%1,%2};" : "=l"(r) : "f"(lo), "f"(hi)); return r;
}
__device__ __forceinline__ void fma2(ull& d, ull a, ull b) {
    asm("fma.rn.f32x2 %0, %1, %2, %0;" : "+l"(d) : "l"(a), "l"(b));
}
__device__ __forceinline__ float2 unpack2(ull v) {
    float2 f; asm("mov.b64 {%0,%1}, %2;" : "=f"(f.x), "=f"(f.y) : "l"(v)); return f;
}

// ---------------- tf32 mma helpers ----------------
__device__ __forceinline__ uint f2tf(float f) {
    uint r; asm("cvt.rna.tf32.f32 %0, %1;" : "=r"(r) : "f"(f)); return r;
}
__device__ __forceinline__ void mma_tf32(float c[4], const uint a[4], uint b0, uint b1) {
    asm("mma.sync.aligned.m16n8k8.row.col.f32.tf32.tf32.f32 "
        "{%0,%1,%2,%3}, {%4,%5,%6,%7}, {%8,%9}, {%0,%1,%2,%3};"
        : "+f"(c[0]), "+f"(c[1]), "+f"(c[2]), "+f"(c[3])
        : "r"(a[0]), "r"(a[1]), "r"(a[2]), "r"(a[3]), "r"(b0), "r"(b1));
}

// ---------------- device scratch (allocation-free rule) ----------------
__device__ float g_q[BB*HH*TT*DD];   // [B,H,T,D], post-RoPE
__device__ float g_k[BB*HH*TT*DD];
__device__ float g_v[BB*HH*TT*DD];
__device__ float g_ao[BB*TT*CC];     // attention output [B,T,C], c = h*64+d
__device__ unsigned int g_cnt[NUNIT];
__device__ unsigned int g_ent_id[NUNIT*NTOK];
__device__ float        g_ent_wt[NUNIT*NTOK];
__device__ float g_part[2ll*3*HH*NTOK*DD];   // [slot][proj][h][tk][d]

__device__ __forceinline__ float gelu_tanh(float t) {
    // 0.5*t*(1+tanh(z)) == t * sigmoid(2z),  z = 0.7978845608*(t + 0.044715 t^3)
    float t3 = t * t * t;
    return t / (1.0f + __expf(-1.5957691216057308f * (t + 0.044715f * t3)));
}

// ---------------------------------------------------------------------------
// Kernel 0: zero the routing counters
// ---------------------------------------------------------------------------
__global__ void zero_cnt_kernel() {
    if (threadIdx.x < NUNIT) g_cnt[threadIdx.x] = 0u;
}

// ---------------------------------------------------------------------------
// Kernel 1: routing. One block per global token, 96 threads (warp = proj).
// ---------------------------------------------------------------------------
__global__ void __launch_bounds__(96) route_kernel(
    const float* __restrict__ x,
    const float* __restrict__ rq, const float* __restrict__ rk,
    const float* __restrict__ rv)
{
    const int tk   = blockIdx.x;
    const int tid  = threadIdx.x;
    const int w    = tid >> 5;
    const int lane = tid & 31;

    __shared__ float xs[CC];
    __shared__ float rs[3][DD*EE];

    for (int i = tid; i < CC/4; i += 96)
        ((float4*)xs)[i] = ((const float4*)(x + (size_t)tk * CC))[i];
    for (int i = tid; i < DD*EE; i += 96) {
        rs[0][i] = rq[i]; rs[1][i] = rk[i]; rs[2][i] = rv[i];
    }
    __syncthreads();

    for (int h = 0; h < HH; h++) {
        float acc = 0.0f;
        if (lane < EE) {
            #pragma unroll 16
            for (int d = 0; d < DD; d++) acc += xs[h*DD + d] * rs[w][d*EE + lane];
        }
        float m1 = NEG_HUGE, m2 = NEG_HUGE;
        int   i1 = 0, i2 = 0;
        #pragma unroll
        for (int e = 0; e < EE; e++) {
            float v = __shfl_sync(0xffffffffu, acc, e);
            if (v > m1)      { m2 = m1; i2 = i1; m1 = v; i1 = e; }
            else if (v > m2) { m2 = v;  i2 = e; }
        }
        if (lane == 0) {
            float dex = expf(m2 - m1);
            float wt1 = 1.0f / (1.0f + dex);
            float wt2 = dex * wt1;
            int base = (w * HH + h) * EE;
            unsigned int p1 = atomicAdd(&g_cnt[base + i1], 1u);
            g_ent_id[(size_t)(base + i1) * NTOK + p1] = (unsigned int)tk;
            g_ent_wt[(size_t)(base + i1) * NTOK + p1] = wt1;
            unsigned int p2 = atomicAdd(&g_cnt[base + i2], 1u);
            g_ent_id[(size_t)(base + i2) * NTOK + p2] = (unsigned int)tk | 0x80000000u;
            g_ent_wt[(size_t)(base + i2) * NTOK + p2] = wt2;
        }
    }
}

// ---------------------------------------------------------------------------
// Kernel 2: expert-grouped MoE GEMM (weights in SMEM, f32x2 packed FMA)
// ---------------------------------------------------------------------------
__global__ void __launch_bounds__(256) moe_gemm_kernel(
    const float* __restrict__ x,
    const float* __restrict__ qw1, const float* __restrict__ qw2,
    const float* __restrict__ kw1, const float* __restrict__ kw2,
    const float* __restrict__ vw1, const float* __restrict__ vw2)
{
    const int gid  = blockIdx.x;
    const int unit = gid / SPLITS;
    const int s    = gid % SPLITS;
    const int proj = unit >> 7;
    const int h    = (unit >> 3) & 15;
    const int e    = unit & 7;

    const float* w1 = ((proj == 0) ? qw1 : (proj == 1) ? kw1 : vw1) + (size_t)e * DD * HID;
    const float* w2 = ((proj == 0) ? qw2 : (proj == 1) ? kw2 : vw2) + (size_t)e * HID * DD;

    extern __shared__ float sm[];
    float* w1s = sm;            // [64][128]
    float* w2s = sm + 8192;     // [128][64]
    float* hs  = sm + 16384;    // [64][128]
    float* xs  = sm + 24576;    // [64][64]
    __shared__ unsigned int stk[64];
    __shared__ float        swt[64];

    const int tid = threadIdx.x;
    const int ty  = tid >> 4;
    const int tx  = tid & 15;

    for (int i = tid; i < 2048; i += 256) {
        ((float4*)w1s)[i] = ((const float4*)w1)[i];
        ((float4*)w2s)[i] = ((const float4*)w2)[i];
    }
    const int nt = (int)g_cnt[unit];
    const size_t ent_base = (size_t)unit * NTOK;

    for (int tile = s; tile * 64 < nt; tile += SPLITS) {
        const int base = tile * 64;
        __syncthreads();
        if (tid < 64) {
            int idx = base + tid;
            if (idx < nt) {
                stk[tid] = g_ent_id[ent_base + idx];
                swt[tid] = g_ent_wt[ent_base + idx];
            } else {
                stk[tid] = 0xFFFFFFFFu;
                swt[tid] = 0.0f;
            }
        }
        __syncthreads();
        {
            int tok = tid >> 2, part = tid & 3;
            unsigned int id = stk[tok];
            if (id != 0xFFFFFFFFu) {
                unsigned int tkk = id & 0x7FFFFFFFu;
                const float4* src = (const float4*)(x + (size_t)tkk * CC + h * DD);
                float4* dst = (float4*)(xs + tok * DD);
                #pragma unroll
                for (int q = 0; q < 4; q++) dst[part*4 + q] = src[part*4 + q];
            }
        }
        __syncthreads();

        ull acc[4][4];
        #pragma unroll
        for (int r = 0; r < 4; r++)
            #pragma unroll
            for (int p = 0; p < 4; p++) acc[r][p] = 0ull;

        #pragma unroll 8
        for (int d = 0; d < 64; d++) {
            ull wv[4];
            #pragma unroll
            for (int p = 0; p < 4; p++)
                wv[p] = *(const ull*)&w1s[d*HID + 2*tx + 32*p];
            #pragma unroll
            for (int r = 0; r < 4; r++) {
                float xv = xs[(ty*4 + r)*DD + d];
                ull xp = pack2(xv, xv);
                #pragma unroll
                for (int p = 0; p < 4; p++) fma2(acc[r][p], xp, wv[p]);
            }
        }
        #pragma unroll
        for (int r = 0; r < 4; r++)
            #pragma unroll
            for (int p = 0; p < 4; p++) {
                float2 v = unpack2(acc[r][p]);
                hs[(ty*4 + r)*HID + 2*tx + 32*p]     = gelu_tanh(v.x);
                hs[(ty*4 + r)*HID + 2*tx + 32*p + 1] = gelu_tanh(v.y);
            }
        __syncthreads();

        ull oc[4][2];
        #pragma unroll
        for (int r = 0; r < 4; r++) { oc[r][0] = 0ull; oc[r][1] = 0ull; }

        #pragma unroll 8
        for (int j = 0; j < HID; j++) {
            ull wp0 = *(const ull*)&w2s[j*DD + 2*tx];
            ull wp1 = *(const ull*)&w2s[j*DD + 2*tx + 32];
            #pragma unroll
            for (int r = 0; r < 4; r++) {
                float hv = hs[(ty*4 + r)*HID + j];
                ull hp = pack2(hv, hv);
                fma2(oc[r][0], hp, wp0);
                fma2(oc[r][1], hp, wp1);
            }
        }
        #pragma unroll
        for (int r = 0; r < 4; r++) {
            int tok = ty*4 + r;
            unsigned int id = stk[tok];
            if (id == 0xFFFFFFFFu) continue;
            unsigned int slot = id >> 31;
            unsigned int tkk  = id & 0x7FFFFFFFu;
            float wt = swt[tok];
            float* dst = g_part + ((((size_t)slot*3 + proj)*HH + h)*NTOK + tkk)*DD;
            float2 v0 = unpack2(oc[r][0]);
            float2 v1 = unpack2(oc[r][1]);
            *(float2*)&dst[2*tx]      = make_float2(wt*v0.x, wt*v0.y);
            *(float2*)&dst[2*tx + 32] = make_float2(wt*v1.x, wt*v1.y);
        }
    }
}

// ---------------------------------------------------------------------------
// Kernel 3: combine both expert slots + RoPE (q,k) -> g_q/g_k/g_v [B,H,T,D]
// ---------------------------------------------------------------------------
__global__ void __launch_bounds__(256) combine_rope_kernel(
    const int* __restrict__ pos_ids,
    const float* __restrict__ cosT, const float* __restrict__ sinT)
{
    const int gw   = blockIdx.x * 8 + (threadIdx.x >> 5);
    const int lane = threadIdx.x & 31;
    const int proj = gw / (HH * NTOK);
    const int rest = gw % (HH * NTOK);
    const int h  = rest / NTOK;
    const int tk = rest % NTOK;

    const size_t SLOT = (size_t)3 * HH * NTOK * DD;
    const size_t pbase = (((size_t)proj * HH + h) * NTOK + tk) * DD;
    float a0 = g_part[pbase + lane]      + g_part[pbase + SLOT + lane];
    float a1 = g_part[pbase + lane + 32] + g_part[pbase + SLOT + lane + 32];

    if (proj < 2) {
        int p = pos_ids[tk];
        float c0 = cosT[p*DD + lane],  c1 = cosT[p*DD + lane + 32];
        float s0 = sinT[p*DD + lane],  s1 = sinT[p*DD + lane + 32];
        float r0 = a0 * c0 - a1 * s0;
        float r1 = a1 * c1 + a0 * s1;
        a0 = r0; a1 = r1;
    }
    int b = tk >> 10, t = tk & 1023;
    float* outg = (proj == 0) ? g_q : (proj == 1) ? g_k : g_v;
    size_t obase = (((size_t)b * HH + h) * TT + t) * DD;
    outg[obase + lane]      = a0;
    outg[obase + lane + 32] = a1;
}

// ---------------------------------------------------------------------------
// Kernel 4: causal flash attention with tf32 mma.sync (m16n8k8).
// 128 threads (4 warps), BQ=64 (16 rows/warp), BK=64.
// smem (tf32 bits): ksm[64][68], vsm[64][72], psm[4][16][68]  = 53248 B
// ---------------------------------------------------------------------------
#define ATTN_SMEM ((4352 + 4608 + 4352) * 4)

__global__ void __launch_bounds__(128) attn_kernel()
{
    extern __shared__ uint smu[];
    uint* ksm = smu;              // [64][68]
    uint* vsm = smu + 4352;       // [64][72]
    uint* psm = smu + 8960;       // [4][16][68]

    const int qt  = blockIdx.x;
    const int bh  = blockIdx.y;
    const int tid  = threadIdx.x;
    const int w    = tid >> 5;
    const int lane = tid & 31;
    const int g    = lane >> 2;    // groupID
    const int tg   = lane & 3;     // threadID_in_group
    uint* pw = psm + w * 1088;

    const float* qg = g_q + (size_t)bh * TT * DD;
    const float* kg = g_k + (size_t)bh * TT * DD;
    const float* vg = g_v + (size_t)bh * TT * DD;
    const int q0 = qt * 64;

    // stage Q (scaled by 1/sqrt(D)) into ksm region, then load fragments
    {
        float* qstage = (float*)ksm;
        for (int i = tid; i < 1024; i += 128) {
            int row = i >> 4, dc = (i & 15) * 4;
            float4 qv = *(const float4*)&qg[(size_t)(q0 + row) * DD + dc];
            qstage[row*68 + dc + 0] = qv.x * 0.125f;
            qstage[row*68 + dc + 1] = qv.y * 0.125f;
            qstage[row*68 + dc + 2] = qv.z * 0.125f;
            qstage[row*68 + dc + 3] = qv.w * 0.125f;
        }
    }
    __syncthreads();
    uint qa[8][4];
    {
        const float* qstage = (const float*)ksm;
        int rA = 16*w + g;
        #pragma unroll
        for (int c = 0; c < 8; c++) {
            qa[c][0] = f2tf(qstage[rA*68     + 8*c + tg]);
            qa[c][1] = f2tf(qstage[(rA+8)*68 + 8*c + tg]);
            qa[c][2] = f2tf(qstage[rA*68     + 8*c + tg + 4]);
            qa[c][3] = f2tf(qstage[(rA+8)*68 + 8*c + tg + 4]);
        }
    }

    float oa[8][4];
    #pragma unroll
    for (int j = 0; j < 8; j++)
        #pragma unroll
        for (int r = 0; r < 4; r++) oa[j][r] = 0.0f;
    float mA = -1e30f, mB = -1e30f, lA = 0.0f, lB = 0.0f;

    for (int kt = 0; kt <= qt; kt++) {
        const int k0 = kt * 64;
        __syncthreads();
        for (int i = tid; i < 1024; i += 128) {
            int row = i >> 4, dc = (i & 15) * 4;
            float4 kv = *(const float4*)&kg[(size_t)(k0 + row) * DD + dc];
            float4 vv = *(const float4*)&vg[(size_t)(k0 + row) * DD + dc];
            ksm[row*68 + dc + 0] = f2tf(kv.x);
            ksm[row*68 + dc + 1] = f2tf(kv.y);
            ksm[row*68 + dc + 2] = f2tf(kv.z);
            ksm[row*68 + dc + 3] = f2tf(kv.w);
            vsm[row*72 + dc + 0] = f2tf(vv.x);
            vsm[row*72 + dc + 1] = f2tf(vv.y);
            vsm[row*72 + dc + 2] = f2tf(vv.z);
            vsm[row*72 + dc + 3] = f2tf(vv.w);
        }
        __syncthreads();

        // ---- QK: scores sc[j][4] for 8 key n-tiles ----
        float sc[8][4];
        #pragma unroll
        for (int j = 0; j < 8; j++)
            #pragma unroll
            for (int r = 0; r < 4; r++) sc[j][r] = 0.0f;

        #pragma unroll
        for (int c = 0; c < 8; c++) {
            #pragma unroll
            for (int j = 0; j < 8; j++) {
                uint b0 = ksm[(8*j + g)*68 + 8*c + tg];
                uint b1 = ksm[(8*j + g)*68 + 8*c + tg + 4];
                mma_tf32(sc[j], qa[c], b0, b1);
            }
        }

        if (kt == qt) {
            const int rA = q0 + 16*w + g, rB = rA + 8;
            #pragma unroll
            for (int j = 0; j < 8; j++) {
                int col = k0 + 8*j + 2*tg;
                if (col     > rA) sc[j][0] = -1e30f;
                if (col + 1 > rA) sc[j][1] = -1e30f;
                if (col     > rB) sc[j][2] = -1e30f;
                if (col + 1 > rB) sc[j][3] = -1e30f;
            }
        }

        // ---- online softmax (rows rA = thread row, rB = +8) ----
        float mtA = -1e30f, mtB = -1e30f;
        #pragma unroll
        for (int j = 0; j < 8; j++) {
            mtA = fmaxf(mtA, fmaxf(sc[j][0], sc[j][1]));
            mtB = fmaxf(mtB, fmaxf(sc[j][2], sc[j][3]));
        }
        mtA = fmaxf(mtA, __shfl_xor_sync(0xffffffffu, mtA, 1));
        mtA = fmaxf(mtA, __shfl_xor_sync(0xffffffffu, mtA, 2));
        mtB = fmaxf(mtB, __shfl_xor_sync(0xffffffffu, mtB, 1));
        mtB = fmaxf(mtB, __shfl_xor_sync(0xffffffffu, mtB, 2));

        float mnA = fmaxf(mA, mtA), mnB = fmaxf(mB, mtB);
        float aA = __expf(mA - mnA), aB = __expf(mB - mnB);
        mA = mnA; mB = mnB;

        float psA = 0.0f, psB = 0.0f;
        #pragma unroll
        for (int j = 0; j < 8; j++) {
            sc[j][0] = __expf(sc[j][0] - mnA);
            sc[j][1] = __expf(sc[j][1] - mnA);
            sc[j][2] = __expf(sc[j][2] - mnB);
            sc[j][3] = __expf(sc[j][3] - mnB);
            psA += sc[j][0] + sc[j][1];
            psB += sc[j][2] + sc[j][3];
        }
        psA += __shfl_xor_sync(0xffffffffu, psA, 1);
        psA += __shfl_xor_sync(0xffffffffu, psA, 2);
        psB += __shfl_xor_sync(0xffffffffu, psB, 1);
        psB += __shfl_xor_sync(0xffffffffu, psB, 2);
        lA = lA * aA + psA;
        lB = lB * aB + psB;

        #pragma unroll
        for (int j = 0; j < 8; j++) {
            oa[j][0] *= aA; oa[j][1] *= aA;
            oa[j][2] *= aB; oa[j][3] *= aB;
        }

        // ---- P -> per-warp smem (tf32) ----
        #pragma unroll
        for (int j = 0; j < 8; j++) {
            pw[g*68     + 8*j + 2*tg]     = f2tf(sc[j][0]);
            pw[g*68     + 8*j + 2*tg + 1] = f2tf(sc[j][1]);
            pw[(g+8)*68 + 8*j + 2*tg]     = f2tf(sc[j][2]);
            pw[(g+8)*68 + 8*j + 2*tg + 1] = f2tf(sc[j][3]);
        }
        __syncwarp();

        // ---- PV: oa += P @ V ----
        #pragma unroll
        for (int c = 0; c < 8; c++) {
            uint pa[4];
            pa[0] = pw[g*68     + 8*c + tg];
            pa[1] = pw[(g+8)*68 + 8*c + tg];
            pa[2] = pw[g*68     + 8*c + tg + 4];
            pa[3] = pw[(g+8)*68 + 8*c + tg + 4];
            #pragma unroll
            for (int jd = 0; jd < 8; jd++) {
                uint b0 = vsm[(8*c + tg)*72     + 8*jd + g];
                uint b1 = vsm[(8*c + tg + 4)*72 + 8*jd + g];
                mma_tf32(oa[jd], pa, b0, b1);
            }
        }
        __syncwarp();
    }

    // ---- epilogue ----
    const int b = bh / HH, h = bh % HH;
    float invA = 1.0f / lA, invB = 1.0f / lB;
    const int rA = q0 + 16*w + g, rB = rA + 8;
    #pragma unroll
    for (int jd = 0; jd < 8; jd++) {
        *(float2*)&g_ao[((size_t)(b * TT) + rA) * CC + h * DD + 8*jd + 2*tg] =
            make_float2(oa[jd][0] * invA, oa[jd][1] * invA);
        *(float2*)&g_ao[((size_t)(b * TT) + rB) * CC + h * DD + 8*jd + 2*tg] =
            make_float2(oa[jd][2] * invB, oa[jd][3] * invB);
    }
}

// ---------------------------------------------------------------------------
// Kernel 5: y = ao @ o_w^T, f32x2 packed.  M=4096, N=1024, K=1024.
// ---------------------------------------------------------------------------
__global__ void __launch_bounds__(256) outproj_kernel(
    const float* __restrict__ ow, float* __restrict__ y)
{
    __shared__ __align__(16) float As[16][64];
    __shared__ __align__(16) float Bs[16][64];

    const int tid = threadIdx.x;
    const int n0 = blockIdx.x * 64;
    const int m0 = blockIdx.y * 64;
    const int tx = tid & 15, ty = tid >> 4;
    const int lr = tid >> 2;
    const int lc = (tid & 3) * 4;

    ull acc2[4][2];
    #pragma unroll
    for (int i = 0; i < 4; i++) { acc2[i][0] = 0ull; acc2[i][1] = 0ull; }

    for (int k0 = 0; k0 < 1024; k0 += 16) {
        float4 a  = *(const float4*)&g_ao[(size_t)(m0 + lr) * 1024 + k0 + lc];
        float4 bv = *(const float4*)&ow  [(size_t)(n0 + lr) * 1024 + k0 + lc];
        As[lc + 0][lr] = a.x;  As[lc + 1][lr] = a.y;
        As[lc + 2][lr] = a.z;  As[lc + 3][lr] = a.w;
        Bs[lc + 0][lr] = bv.x; Bs[lc + 1][lr] = bv.y;
        Bs[lc + 2][lr] = bv.z; Bs[lc + 3][lr] = bv.w;
        __syncthreads();

        #pragma unroll
        for (int kk = 0; kk < 16; kk++) {
            float4 av = *(const float4*)&As[kk][ty * 4];
            float4 bw = *(const float4*)&Bs[kk][tx * 4];
            ull b0 = pack2(bw.x, bw.y);
            ull b1 = pack2(bw.z, bw.w);
            ull a0 = pack2(av.x, av.x);
            ull a1 = pack2(av.y, av.y);
            ull a2 = pack2(av.z, av.z);
            ull a3 = pack2(av.w, av.w);
            fma2(acc2[0][0], a0, b0); fma2(acc2[0][1], a0, b1);
            fma2(acc2[1][0], a1, b0); fma2(acc2[1][1], a1, b1);
            fma2(acc2[2][0], a2, b0); fma2(acc2[2][1], a2, b1);
            fma2(acc2[3][0], a3, b0); fma2(acc2[3][1], a3, b1);
        }
        __syncthreads();
    }

    #pragma unroll
    for (int i = 0; i < 4; i++) {
        float2 lo = unpack2(acc2[i][0]);
        float2 hi = unpack2(acc2[i][1]);
        *(float4*)&y[(size_t)(m0 + ty * 4 + i) * 1024 + n0 + tx * 4] =
            make_float4(lo.x, lo.y, hi.x, hi.y);
    }
}

// ---------------------------------------------------------------------------
extern "C" void kernel_launch(void* const* d_in, const int* in_sizes, int n_in,
                              void* d_out, int out_size)
{
    const float* x    = (const float*)d_in[0];
    const int*   pid  = (const int*)  d_in[1];
    const float* cosT = (const float*)d_in[2];
    const float* sinT = (const float*)d_in[3];
    const float* rq   = (const float*)d_in[4];
    const float* rk   = (const float*)d_in[5];
    const float* rv   = (const float*)d_in[6];
    const float* qw1  = (const float*)d_in[7];
    const float* qw2  = (const float*)d_in[8];
    const float* kw1  = (const float*)d_in[9];
    const float* kw2  = (const float*)d_in[10];
    const float* vw1  = (const float*)d_in[11];
    const float* vw2  = (const float*)d_in[12];
    const float* ow   = (const float*)d_in[13];
    float* y = (float*)d_out;

    static const int MOE_SMEM = (8192 + 8192 + 8192 + 4096) * 4;  // 114688 B
    cudaFuncSetAttribute(moe_gemm_kernel,
                         cudaFuncAttributeMaxDynamicSharedMemorySize, MOE_SMEM);
    cudaFuncSetAttribute(attn_kernel,
                         cudaFuncAttributeMaxDynamicSharedMemorySize, ATTN_SMEM);

    zero_cnt_kernel<<<1, 512>>>();
    route_kernel<<<NTOK, 96>>>(x, rq, rk, rv);
    moe_gemm_kernel<<<NUNIT * SPLITS, 256, MOE_SMEM>>>(x, qw1, qw2, kw1, kw2, vw1, vw2);
    combine_rope_kernel<<<(3 * HH * NTOK) / 8, 256>>>(pid, cosT, sinT);

    dim3 g2(TT / 64, BB * HH);
    attn_kernel<<<g2, 128, ATTN_SMEM>>>();

    dim3 g3(CC / 64, (BB * TT) / 64);
    outproj_kernel<<<g3, 256>>>(ow, y);
}

// round 4
// speedup vs baseline: 2.2936x; 1.2847x over previous
#include <cuda_runtime.h>
#include <cuda_bf16.h>
#include <math.h>

#define BB 4
#define TT 1024
#define CC 1024
#define HH 16
#define DD 64
#define EE 8
#define HID 128
#define NTOK (BB*TT)          // 4096 global tokens
#define NUNIT (3*HH*EE)       // 384 (proj, head, expert) units
#define SPLITS 4

#define NEG_HUGE (-3.38953139e38f)

typedef unsigned long long ull;
typedef unsigned int uint;

// ---------------- tf32 mma helpers ----------------
__device__ __forceinline__ uint f2tf(float f) {
    uint r; asm("cvt.rna.tf32.f32 %0, %1;" : "=r"(r) : "f"(f)); return r;
}
__device__ __forceinline__ void mma_tf32(float c[4], const uint a[4], uint b0, uint b1) {
    asm("mma.sync.aligned.m16n8k8.row.col.f32.tf32.tf32.f32 "
        "{%0,%1,%2,%3}, {%4,%5,%6,%7}, {%8,%9}, {%0,%1,%2,%3};"
        : "+f"(c[0]), "+f"(c[1]), "+f"(c[2]), "+f"(c[3])
        : "r"(a[0]), "r"(a[1]), "r"(a[2]), "r"(a[3]), "r"(b0), "r"(b1));
}

// ---------------- device scratch (allocation-free rule) ----------------
__device__ float g_q[BB*HH*TT*DD];   // [B,H,T,D], post-RoPE
__device__ float g_k[BB*HH*TT*DD];
__device__ float g_v[BB*HH*TT*DD];
__device__ float g_ao[BB*TT*CC];     // attention output [B,T,C], c = h*64+d
__device__ unsigned int g_cnt[NUNIT];
__device__ unsigned int g_ent_id[NUNIT*NTOK];
__device__ float        g_ent_wt[NUNIT*NTOK];
__device__ float g_part[2ll*3*HH*NTOK*DD];   // [slot][proj][h][tk][d]

__device__ __forceinline__ float gelu_tanh(float t) {
    // 0.5*t*(1+tanh(z)) == t * sigmoid(2z),  z = 0.7978845608*(t + 0.044715 t^3)
    float t3 = t * t * t;
    return t / (1.0f + __expf(-1.5957691216057308f * (t + 0.044715f * t3)));
}

// ---------------------------------------------------------------------------
// Kernel 0: zero the routing counters
// ---------------------------------------------------------------------------
__global__ void zero_cnt_kernel() {
    if (threadIdx.x < NUNIT) g_cnt[threadIdx.x] = 0u;
}

// ---------------------------------------------------------------------------
// Kernel 1: routing. One block per global token, 96 threads (warp = proj).
// ---------------------------------------------------------------------------
__global__ void __launch_bounds__(96) route_kernel(
    const float* __restrict__ x,
    const float* __restrict__ rq, const float* __restrict__ rk,
    const float* __restrict__ rv)
{
    const int tk   = blockIdx.x;
    const int tid  = threadIdx.x;
    const int w    = tid >> 5;
    const int lane = tid & 31;

    __shared__ float xs[CC];
    __shared__ float rs[3][DD*EE];

    for (int i = tid; i < CC/4; i += 96)
        ((float4*)xs)[i] = ((const float4*)(x + (size_t)tk * CC))[i];
    for (int i = tid; i < DD*EE; i += 96) {
        rs[0][i] = rq[i]; rs[1][i] = rk[i]; rs[2][i] = rv[i];
    }
    __syncthreads();

    for (int h = 0; h < HH; h++) {
        float acc = 0.0f;
        if (lane < EE) {
            #pragma unroll 16
            for (int d = 0; d < DD; d++) acc += xs[h*DD + d] * rs[w][d*EE + lane];
        }
        float m1 = NEG_HUGE, m2 = NEG_HUGE;
        int   i1 = 0, i2 = 0;
        #pragma unroll
        for (int e = 0; e < EE; e++) {
            float v = __shfl_sync(0xffffffffu, acc, e);
            if (v > m1)      { m2 = m1; i2 = i1; m1 = v; i1 = e; }
            else if (v > m2) { m2 = v;  i2 = e; }
        }
        if (lane == 0) {
            float dex = expf(m2 - m1);
            float wt1 = 1.0f / (1.0f + dex);
            float wt2 = dex * wt1;
            int base = (w * HH + h) * EE;
            unsigned int p1 = atomicAdd(&g_cnt[base + i1], 1u);
            g_ent_id[(size_t)(base + i1) * NTOK + p1] = (unsigned int)tk;
            g_ent_wt[(size_t)(base + i1) * NTOK + p1] = wt1;
            unsigned int p2 = atomicAdd(&g_cnt[base + i2], 1u);
            g_ent_id[(size_t)(base + i2) * NTOK + p2] = (unsigned int)tk | 0x80000000u;
            g_ent_wt[(size_t)(base + i2) * NTOK + p2] = wt2;
        }
    }
}

// ---------------------------------------------------------------------------
// Kernel 2: expert-grouped MoE GEMM on tf32 mma.sync.
// Per 64-token tile:  stage1 H = gelu(X[64x64] @ W1[64x128]),
//                     stage2 O = H[64x128] @ W2[128x64].
// 256 threads = 8 warps; warp (wm = w&3 -> 16 rows, wn = w>>2 -> col half).
// smem strides 68/132 give bank = (4g+tg)%32 (conflict-free fragment loads).
// ---------------------------------------------------------------------------
#define MOE_SMEM ((128*68 + 64*132 + 64*132 + 64*68) * 4)   // 119808 B

__global__ void __launch_bounds__(256) moe_gemm_kernel(
    const float* __restrict__ x,
    const float* __restrict__ qw1, const float* __restrict__ qw2,
    const float* __restrict__ kw1, const float* __restrict__ kw2,
    const float* __restrict__ vw1, const float* __restrict__ vw2)
{
    const int gid  = blockIdx.x;
    const int unit = gid / SPLITS;
    const int s    = gid % SPLITS;
    const int proj = unit >> 7;
    const int h    = (unit >> 3) & 15;
    const int e    = unit & 7;

    const float* w1 = ((proj == 0) ? qw1 : (proj == 1) ? kw1 : vw1) + (size_t)e * DD * HID;
    const float* w2 = ((proj == 0) ? qw2 : (proj == 1) ? kw2 : vw2) + (size_t)e * HID * DD;

    extern __shared__ uint smu[];
    uint* w1t = smu;                    // [128][68]  w1t[f*68 + d]
    uint* w2t = smu + 128*68;           // [64][132]  w2t[d*132 + j]
    uint* hsm = w2t + 64*132;           // [64][132]  hsm[tok*132 + j]
    uint* xsm = hsm + 64*132;           // [64][68]   xsm[tok*68 + d]
    __shared__ unsigned int stk[64];
    __shared__ float        swt[64];

    const int tid  = threadIdx.x;
    const int w    = tid >> 5;
    const int lane = tid & 31;
    const int g    = lane >> 2;
    const int tg   = lane & 3;
    const int wm   = w & 3;       // token group of 16
    const int wn   = w >> 2;      // column half

    // one-time transposed weight load (tf32)
    for (int i = tid; i < DD*HID; i += 256) {
        int d = i >> 7, f = i & 127;
        w1t[f*68 + d] = f2tf(w1[i]);
    }
    for (int i = tid; i < HID*DD; i += 256) {
        int j = i >> 6, d = i & 63;
        w2t[d*132 + j] = f2tf(w2[i]);
    }

    const int nt = (int)g_cnt[unit];
    const size_t ent_base = (size_t)unit * NTOK;

    for (int tile = s; tile * 64 < nt; tile += SPLITS) {
        const int base = tile * 64;
        __syncthreads();
        if (tid < 64) {
            int idx = base + tid;
            if (idx < nt) {
                stk[tid] = g_ent_id[ent_base + idx];
                swt[tid] = g_ent_wt[ent_base + idx];
            } else {
                stk[tid] = 0xFFFFFFFFu;
                swt[tid] = 0.0f;
            }
        }
        __syncthreads();
        {   // gather x rows -> xsm (tf32): 4 threads per token, 16 elems each
            int tok = tid >> 2, part = tid & 3;
            unsigned int id = stk[tok];
            if (id != 0xFFFFFFFFu) {
                unsigned int tkk = id & 0x7FFFFFFFu;
                const float* src = x + (size_t)tkk * CC + h * DD + part * 16;
                uint* dst = xsm + tok * 68 + part * 16;
                #pragma unroll
                for (int q = 0; q < 16; q++) dst[q] = f2tf(src[q]);
            }
        }
        __syncthreads();

        // ---- stage 1: H = gelu(X @ W1) ----
        float c1[8][4];
        #pragma unroll
        for (int j = 0; j < 8; j++)
            #pragma unroll
            for (int r = 0; r < 4; r++) c1[j][r] = 0.0f;

        #pragma unroll
        for (int c = 0; c < 8; c++) {
            uint a[4];
            a[0] = xsm[(16*wm + g)    *68 + 8*c + tg];
            a[1] = xsm[(16*wm + g + 8)*68 + 8*c + tg];
            a[2] = xsm[(16*wm + g)    *68 + 8*c + tg + 4];
            a[3] = xsm[(16*wm + g + 8)*68 + 8*c + tg + 4];
            #pragma unroll
            for (int j = 0; j < 8; j++) {
                uint b0 = w1t[(64*wn + 8*j + g)*68 + 8*c + tg];
                uint b1 = w1t[(64*wn + 8*j + g)*68 + 8*c + tg + 4];
                mma_tf32(c1[j], a, b0, b1);
            }
        }
        #pragma unroll
        for (int j = 0; j < 8; j++) {
            int col = 64*wn + 8*j + 2*tg;
            hsm[(16*wm + g)    *132 + col]     = f2tf(gelu_tanh(c1[j][0]));
            hsm[(16*wm + g)    *132 + col + 1] = f2tf(gelu_tanh(c1[j][1]));
            hsm[(16*wm + g + 8)*132 + col]     = f2tf(gelu_tanh(c1[j][2]));
            hsm[(16*wm + g + 8)*132 + col + 1] = f2tf(gelu_tanh(c1[j][3]));
        }
        __syncthreads();

        // ---- stage 2: O = H @ W2 ----
        float c2[4][4];
        #pragma unroll
        for (int j = 0; j < 4; j++)
            #pragma unroll
            for (int r = 0; r < 4; r++) c2[j][r] = 0.0f;

        #pragma unroll
        for (int c = 0; c < 16; c++) {
            uint a[4];
            a[0] = hsm[(16*wm + g)    *132 + 8*c + tg];
            a[1] = hsm[(16*wm + g + 8)*132 + 8*c + tg];
            a[2] = hsm[(16*wm + g)    *132 + 8*c + tg + 4];
            a[3] = hsm[(16*wm + g + 8)*132 + 8*c + tg + 4];
            #pragma unroll
            for (int j = 0; j < 4; j++) {
                uint b0 = w2t[(32*wn + 8*j + g)*132 + 8*c + tg];
                uint b1 = w2t[(32*wn + 8*j + g)*132 + 8*c + tg + 4];
                mma_tf32(c2[j], a, b0, b1);
            }
        }

        // epilogue: scale by routing weight, scatter to g_part
        int tokA = 16*wm + g, tokB = tokA + 8;
        unsigned int idA = stk[tokA], idB = stk[tokB];
        if (idA != 0xFFFFFFFFu) {
            float wt = swt[tokA];
            unsigned int slot = idA >> 31, tkk = idA & 0x7FFFFFFFu;
            float* dst = g_part + ((((size_t)slot*3 + proj)*HH + h)*NTOK + tkk)*DD;
            #pragma unroll
            for (int j = 0; j < 4; j++)
                *(float2*)&dst[32*wn + 8*j + 2*tg] =
                    make_float2(wt*c2[j][0], wt*c2[j][1]);
        }
        if (idB != 0xFFFFFFFFu) {
            float wt = swt[tokB];
            unsigned int slot = idB >> 31, tkk = idB & 0x7FFFFFFFu;
            float* dst = g_part + ((((size_t)slot*3 + proj)*HH + h)*NTOK + tkk)*DD;
            #pragma unroll
            for (int j = 0; j < 4; j++)
                *(float2*)&dst[32*wn + 8*j + 2*tg] =
                    make_float2(wt*c2[j][2], wt*c2[j][3]);
        }
    }
}

// ---------------------------------------------------------------------------
// Kernel 3: combine both expert slots + RoPE (q,k) -> g_q/g_k/g_v [B,H,T,D]
// ---------------------------------------------------------------------------
__global__ void __launch_bounds__(256) combine_rope_kernel(
    const int* __restrict__ pos_ids,
    const float* __restrict__ cosT, const float* __restrict__ sinT)
{
    const int gw   = blockIdx.x * 8 + (threadIdx.x >> 5);
    const int lane = threadIdx.x & 31;
    const int proj = gw / (HH * NTOK);
    const int rest = gw % (HH * NTOK);
    const int h  = rest / NTOK;
    const int tk = rest % NTOK;

    const size_t SLOT = (size_t)3 * HH * NTOK * DD;
    const size_t pbase = (((size_t)proj * HH + h) * NTOK + tk) * DD;
    float a0 = g_part[pbase + lane]      + g_part[pbase + SLOT + lane];
    float a1 = g_part[pbase + lane + 32] + g_part[pbase + SLOT + lane + 32];

    if (proj < 2) {
        int p = pos_ids[tk];
        float c0 = cosT[p*DD + lane],  c1 = cosT[p*DD + lane + 32];
        float s0 = sinT[p*DD + lane],  s1 = sinT[p*DD + lane + 32];
        float r0 = a0 * c0 - a1 * s0;
        float r1 = a1 * c1 + a0 * s1;
        a0 = r0; a1 = r1;
    }
    int b = tk >> 10, t = tk & 1023;
    float* outg = (proj == 0) ? g_q : (proj == 1) ? g_k : g_v;
    size_t obase = (((size_t)b * HH + h) * TT + t) * DD;
    outg[obase + lane]      = a0;
    outg[obase + lane + 32] = a1;
}

// ---------------------------------------------------------------------------
// Kernel 4: causal flash attention with tf32 mma.sync (m16n8k8).
// ---------------------------------------------------------------------------
#define ATTN_SMEM ((4352 + 4608 + 4352) * 4)

__global__ void __launch_bounds__(128) attn_kernel()
{
    extern __shared__ uint smu[];
    uint* ksm = smu;              // [64][68]
    uint* vsm = smu + 4352;       // [64][72]
    uint* psm = smu + 8960;       // [4][16][68]

    const int qt  = blockIdx.x;
    const int bh  = blockIdx.y;
    const int tid  = threadIdx.x;
    const int w    = tid >> 5;
    const int lane = tid & 31;
    const int g    = lane >> 2;
    const int tg   = lane & 3;
    uint* pw = psm + w * 1088;

    const float* qg = g_q + (size_t)bh * TT * DD;
    const float* kg = g_k + (size_t)bh * TT * DD;
    const float* vg = g_v + (size_t)bh * TT * DD;
    const int q0 = qt * 64;

    {
        float* qstage = (float*)ksm;
        for (int i = tid; i < 1024; i += 128) {
            int row = i >> 4, dc = (i & 15) * 4;
            float4 qv = *(const float4*)&qg[(size_t)(q0 + row) * DD + dc];
            qstage[row*68 + dc + 0] = qv.x * 0.125f;
            qstage[row*68 + dc + 1] = qv.y * 0.125f;
            qstage[row*68 + dc + 2] = qv.z * 0.125f;
            qstage[row*68 + dc + 3] = qv.w * 0.125f;
        }
    }
    __syncthreads();
    uint qa[8][4];
    {
        const float* qstage = (const float*)ksm;
        int rA = 16*w + g;
        #pragma unroll
        for (int c = 0; c < 8; c++) {
            qa[c][0] = f2tf(qstage[rA*68     + 8*c + tg]);
            qa[c][1] = f2tf(qstage[(rA+8)*68 + 8*c + tg]);
            qa[c][2] = f2tf(qstage[rA*68     + 8*c + tg + 4]);
            qa[c][3] = f2tf(qstage[(rA+8)*68 + 8*c + tg + 4]);
        }
    }

    float oa[8][4];
    #pragma unroll
    for (int j = 0; j < 8; j++)
        #pragma unroll
        for (int r = 0; r < 4; r++) oa[j][r] = 0.0f;
    float mA = -1e30f, mB = -1e30f, lA = 0.0f, lB = 0.0f;

    for (int kt = 0; kt <= qt; kt++) {
        const int k0 = kt * 64;
        __syncthreads();
        for (int i = tid; i < 1024; i += 128) {
            int row = i >> 4, dc = (i & 15) * 4;
            float4 kv = *(const float4*)&kg[(size_t)(k0 + row) * DD + dc];
            float4 vv = *(const float4*)&vg[(size_t)(k0 + row) * DD + dc];
            ksm[row*68 + dc + 0] = f2tf(kv.x);
            ksm[row*68 + dc + 1] = f2tf(kv.y);
            ksm[row*68 + dc + 2] = f2tf(kv.z);
            ksm[row*68 + dc + 3] = f2tf(kv.w);
            vsm[row*72 + dc + 0] = f2tf(vv.x);
            vsm[row*72 + dc + 1] = f2tf(vv.y);
            vsm[row*72 + dc + 2] = f2tf(vv.z);
            vsm[row*72 + dc + 3] = f2tf(vv.w);
        }
        __syncthreads();

        float sc[8][4];
        #pragma unroll
        for (int j = 0; j < 8; j++)
            #pragma unroll
            for (int r = 0; r < 4; r++) sc[j][r] = 0.0f;

        #pragma unroll
        for (int c = 0; c < 8; c++) {
            #pragma unroll
            for (int j = 0; j < 8; j++) {
                uint b0 = ksm[(8*j + g)*68 + 8*c + tg];
                uint b1 = ksm[(8*j + g)*68 + 8*c + tg + 4];
                mma_tf32(sc[j], qa[c], b0, b1);
            }
        }

        if (kt == qt) {
            const int rA = q0 + 16*w + g, rB = rA + 8;
            #pragma unroll
            for (int j = 0; j < 8; j++) {
                int col = k0 + 8*j + 2*tg;
                if (col     > rA) sc[j][0] = -1e30f;
                if (col + 1 > rA) sc[j][1] = -1e30f;
                if (col     > rB) sc[j][2] = -1e30f;
                if (col + 1 > rB) sc[j][3] = -1e30f;
            }
        }

        float mtA = -1e30f, mtB = -1e30f;
        #pragma unroll
        for (int j = 0; j < 8; j++) {
            mtA = fmaxf(mtA, fmaxf(sc[j][0], sc[j][1]));
            mtB = fmaxf(mtB, fmaxf(sc[j][2], sc[j][3]));
        }
        mtA = fmaxf(mtA, __shfl_xor_sync(0xffffffffu, mtA, 1));
        mtA = fmaxf(mtA, __shfl_xor_sync(0xffffffffu, mtA, 2));
        mtB = fmaxf(mtB, __shfl_xor_sync(0xffffffffu, mtB, 1));
        mtB = fmaxf(mtB, __shfl_xor_sync(0xffffffffu, mtB, 2));

        float mnA = fmaxf(mA, mtA), mnB = fmaxf(mB, mtB);
        float aA = __expf(mA - mnA), aB = __expf(mB - mnB);
        mA = mnA; mB = mnB;

        float psA = 0.0f, psB = 0.0f;
        #pragma unroll
        for (int j = 0; j < 8; j++) {
            sc[j][0] = __expf(sc[j][0] - mnA);
            sc[j][1] = __expf(sc[j][1] - mnA);
            sc[j][2] = __expf(sc[j][2] - mnB);
            sc[j][3] = __expf(sc[j][3] - mnB);
            psA += sc[j][0] + sc[j][1];
            psB += sc[j][2] + sc[j][3];
        }
        psA += __shfl_xor_sync(0xffffffffu, psA, 1);
        psA += __shfl_xor_sync(0xffffffffu, psA, 2);
        psB += __shfl_xor_sync(0xffffffffu, psB, 1);
        psB += __shfl_xor_sync(0xffffffffu, psB, 2);
        lA = lA * aA + psA;
        lB = lB * aB + psB;

        #pragma unroll
        for (int j = 0; j < 8; j++) {
            oa[j][0] *= aA; oa[j][1] *= aA;
            oa[j][2] *= aB; oa[j][3] *= aB;
        }

        #pragma unroll
        for (int j = 0; j < 8; j++) {
            pw[g*68     + 8*j + 2*tg]     = f2tf(sc[j][0]);
            pw[g*68     + 8*j + 2*tg + 1] = f2tf(sc[j][1]);
            pw[(g+8)*68 + 8*j + 2*tg]     = f2tf(sc[j][2]);
            pw[(g+8)*68 + 8*j + 2*tg + 1] = f2tf(sc[j][3]);
        }
        __syncwarp();

        #pragma unroll
        for (int c = 0; c < 8; c++) {
            uint pa[4];
            pa[0] = pw[g*68     + 8*c + tg];
            pa[1] = pw[(g+8)*68 + 8*c + tg];
            pa[2] = pw[g*68     + 8*c + tg + 4];
            pa[3] = pw[(g+8)*68 + 8*c + tg + 4];
            #pragma unroll
            for (int jd = 0; jd < 8; jd++) {
                uint b0 = vsm[(8*c + tg)*72     + 8*jd + g];
                uint b1 = vsm[(8*c + tg + 4)*72 + 8*jd + g];
                mma_tf32(oa[jd], pa, b0, b1);
            }
        }
        __syncwarp();
    }

    const int b = bh / HH, h = bh % HH;
    float invA = 1.0f / lA, invB = 1.0f / lB;
    const int rA = q0 + 16*w + g, rB = rA + 8;
    #pragma unroll
    for (int jd = 0; jd < 8; jd++) {
        *(float2*)&g_ao[((size_t)(b * TT) + rA) * CC + h * DD + 8*jd + 2*tg] =
            make_float2(oa[jd][0] * invA, oa[jd][1] * invA);
        *(float2*)&g_ao[((size_t)(b * TT) + rB) * CC + h * DD + 8*jd + 2*tg] =
            make_float2(oa[jd][2] * invB, oa[jd][3] * invB);
    }
}

// ---------------------------------------------------------------------------
// Kernel 5: y = ao @ ow^T on tf32 mma.  BM=128, BN=64, BK=32, 256 threads.
// as[128][36], bs[64][36] (bank = (4g+tg)%32, conflict-free).
// ---------------------------------------------------------------------------
__global__ void __launch_bounds__(256) outproj_kernel(
    const float* __restrict__ ow, float* __restrict__ y)
{
    __shared__ uint as[128*36];
    __shared__ uint bs[64*36];

    const int tid  = threadIdx.x;
    const int w    = tid >> 5;      // warp 0..7 -> m group of 16
    const int lane = tid & 31;
    const int g    = lane >> 2;
    const int tg   = lane & 3;
    const int n0 = blockIdx.x * 64;
    const int m0 = blockIdx.y * 128;

    float acc[8][4];
    #pragma unroll
    for (int j = 0; j < 8; j++)
        #pragma unroll
        for (int r = 0; r < 4; r++) acc[j][r] = 0.0f;

    for (int k0 = 0; k0 < 1024; k0 += 32) {
        __syncthreads();
        // A tile: 128 rows x 32 k (1024 float4, 4 per thread)
        #pragma unroll
        for (int it = 0; it < 4; it++) {
            int idx = tid + it * 256;
            int row = idx >> 3, c4 = (idx & 7) * 4;
            float4 v = *(const float4*)&g_ao[(size_t)(m0 + row) * 1024 + k0 + c4];
            uint* d = &as[row*36 + c4];
            d[0] = f2tf(v.x); d[1] = f2tf(v.y); d[2] = f2tf(v.z); d[3] = f2tf(v.w);
        }
        // B tile: 64 rows x 32 k (512 float4, 2 per thread)
        #pragma unroll
        for (int it = 0; it < 2; it++) {
            int idx = tid + it * 256;
            int row = idx >> 3, c4 = (idx & 7) * 4;
            float4 v = *(const float4*)&ow[(size_t)(n0 + row) * 1024 + k0 + c4];
            uint* d = &bs[row*36 + c4];
            d[0] = f2tf(v.x); d[1] = f2tf(v.y); d[2] = f2tf(v.z); d[3] = f2tf(v.w);
        }
        __syncthreads();

        #pragma unroll
        for (int c = 0; c < 4; c++) {
            uint a[4];
            a[0] = as[(16*w + g)    *36 + 8*c + tg];
            a[1] = as[(16*w + g + 8)*36 + 8*c + tg];
            a[2] = as[(16*w + g)    *36 + 8*c + tg + 4];
            a[3] = as[(16*w + g + 8)*36 + 8*c + tg + 4];
            #pragma unroll
            for (int j = 0; j < 8; j++) {
                uint b0 = bs[(8*j + g)*36 + 8*c + tg];
                uint b1 = bs[(8*j + g)*36 + 8*c + tg + 4];
                mma_tf32(acc[j], a, b0, b1);
            }
        }
    }

    const int rA = m0 + 16*w + g, rB = rA + 8;
    #pragma unroll
    for (int j = 0; j < 8; j++) {
        *(float2*)&y[(size_t)rA * 1024 + n0 + 8*j + 2*tg] =
            make_float2(acc[j][0], acc[j][1]);
        *(float2*)&y[(size_t)rB * 1024 + n0 + 8*j + 2*tg] =
            make_float2(acc[j][2], acc[j][3]);
    }
}

// ---------------------------------------------------------------------------
extern "C" void kernel_launch(void* const* d_in, const int* in_sizes, int n_in,
                              void* d_out, int out_size)
{
    const float* x    = (const float*)d_in[0];
    const int*   pid  = (const int*)  d_in[1];
    const float* cosT = (const float*)d_in[2];
    const float* sinT = (const float*)d_in[3];
    const float* rq   = (const float*)d_in[4];
    const float* rk   = (const float*)d_in[5];
    const float* rv   = (const float*)d_in[6];
    const float* qw1  = (const float*)d_in[7];
    const float* qw2  = (const float*)d_in[8];
    const float* kw1  = (const float*)d_in[9];
    const float* kw2  = (const float*)d_in[10];
    const float* vw1  = (const float*)d_in[11];
    const float* vw2  = (const float*)d_in[12];
    const float* ow   = (const float*)d_in[13];
    float* y = (float*)d_out;

    cudaFuncSetAttribute(moe_gemm_kernel,
                         cudaFuncAttributeMaxDynamicSharedMemorySize, MOE_SMEM);
    cudaFuncSetAttribute(attn_kernel,
                         cudaFuncAttributeMaxDynamicSharedMemorySize, ATTN_SMEM);

    zero_cnt_kernel<<<1, 512>>>();
    route_kernel<<<NTOK, 96>>>(x, rq, rk, rv);
    moe_gemm_kernel<<<NUNIT * SPLITS, 256, MOE_SMEM>>>(x, qw1, qw2, kw1, kw2, vw1, vw2);
    combine_rope_kernel<<<(3 * HH * NTOK) / 8, 256>>>(pid, cosT, sinT);

    dim3 g2(TT / 64, BB * HH);
    attn_kernel<<<g2, 128, ATTN_SMEM>>>();

    dim3 g3(CC / 64, (BB * TT) / 128);
    outproj_kernel<<<g3, 256>>>(ow, y);
}

// round 5
// speedup vs baseline: 2.3873x; 1.0409x over previous
#include <cuda_runtime.h>
#include <cuda_bf16.h>
#include <math.h>

#define BB 4
#define TT 1024
#define CC 1024
#define HH 16
#define DD 64
#define EE 8
#define HID 128
#define NTOK (BB*TT)          // 4096 global tokens
#define NUNIT (3*HH*EE)       // 384 (proj, head, expert) units
#define SPLITS 8

#define NEG_HUGE (-3.38953139e38f)

typedef unsigned long long ull;
typedef unsigned int uint;

// ---------------- tf32 mma helpers ----------------
__device__ __forceinline__ uint f2tf(float f) {
    uint r; asm("cvt.rna.tf32.f32 %0, %1;" : "=r"(r) : "f"(f)); return r;
}
__device__ __forceinline__ void mma_tf32(float c[4], const uint a[4], uint b0, uint b1) {
    asm("mma.sync.aligned.m16n8k8.row.col.f32.tf32.tf32.f32 "
        "{%0,%1,%2,%3}, {%4,%5,%6,%7}, {%8,%9}, {%0,%1,%2,%3};"
        : "+f"(c[0]), "+f"(c[1]), "+f"(c[2]), "+f"(c[3])
        : "r"(a[0]), "r"(a[1]), "r"(a[2]), "r"(a[3]), "r"(b0), "r"(b1));
}
__device__ __forceinline__ void cpa16(uint dst, const void* src) {
    asm volatile("cp.async.cg.shared.global [%0], [%1], 16;" :: "r"(dst), "l"(src));
}

// ---------------- device scratch (allocation-free rule) ----------------
__device__ float g_q[BB*HH*TT*DD];   // [B,H,T,D], post-RoPE, tf32 bits, pre-scaled
__device__ float g_k[BB*HH*TT*DD];   // tf32 bits
__device__ float g_v[BB*HH*TT*DD];   // tf32 bits
__device__ float g_ao[BB*TT*CC];     // attention output [B,T,C], c = h*64+d
__device__ unsigned int g_cnt[NUNIT];
__device__ unsigned int g_ent_id[NUNIT*NTOK];
__device__ float        g_ent_wt[NUNIT*NTOK];
__device__ float g_part[2ll*3*HH*NTOK*DD];   // [slot][proj][h][tk][d]

__device__ __forceinline__ float gelu_tanh(float t) {
    float t3 = t * t * t;
    return t / (1.0f + __expf(-1.5957691216057308f * (t + 0.044715f * t3)));
}

// ---------------------------------------------------------------------------
// Kernel 0: zero the routing counters
// ---------------------------------------------------------------------------
__global__ void zero_cnt_kernel() {
    if (threadIdx.x < NUNIT) g_cnt[threadIdx.x] = 0u;
}

// ---------------------------------------------------------------------------
// Kernel 1: routing. One block per token, 96 threads (warp = proj).
// Lane layout: e = lane&7, hq = lane>>3; 4 head-batches of 4 heads.
// ---------------------------------------------------------------------------
__global__ void __launch_bounds__(96) route_kernel(
    const float* __restrict__ x,
    const float* __restrict__ rq, const float* __restrict__ rk,
    const float* __restrict__ rv)
{
    const int tk   = blockIdx.x;
    const int tid  = threadIdx.x;
    const int w    = tid >> 5;
    const int lane = tid & 31;
    const int e    = lane & 7;
    const int hq   = lane >> 3;     // 0..3

    __shared__ float xs[CC];
    __shared__ float rs[3][DD*EE];

    for (int i = tid; i < CC/4; i += 96)
        ((float4*)xs)[i] = ((const float4*)(x + (size_t)tk * CC))[i];
    for (int i = tid; i < DD*EE; i += 96) {
        rs[0][i] = rq[i]; rs[1][i] = rk[i]; rs[2][i] = rv[i];
    }
    __syncthreads();

    const float* rw = rs[w];
    for (int hb = 0; hb < 4; hb++) {
        int h = hb * 4 + hq;
        float acc = 0.0f;
        #pragma unroll 16
        for (int d = 0; d < DD; d++) acc += xs[h*DD + d] * rw[d*EE + e];

        float m1 = NEG_HUGE, m2 = NEG_HUGE;
        int   i1 = 0, i2 = 0;
        #pragma unroll
        for (int ee = 0; ee < EE; ee++) {
            float v = __shfl_sync(0xffffffffu, acc, hq*8 + ee);
            if (v > m1)      { m2 = m1; i2 = i1; m1 = v; i1 = ee; }
            else if (v > m2) { m2 = v;  i2 = ee; }
        }
        if (e == 0) {
            float dex = expf(m2 - m1);
            float wt1 = 1.0f / (1.0f + dex);
            float wt2 = dex * wt1;
            int base = (w * HH + h) * EE;
            unsigned int p1 = atomicAdd(&g_cnt[base + i1], 1u);
            g_ent_id[(size_t)(base + i1) * NTOK + p1] = (unsigned int)tk;
            g_ent_wt[(size_t)(base + i1) * NTOK + p1] = wt1;
            unsigned int p2 = atomicAdd(&g_cnt[base + i2], 1u);
            g_ent_id[(size_t)(base + i2) * NTOK + p2] = (unsigned int)tk | 0x80000000u;
            g_ent_wt[(size_t)(base + i2) * NTOK + p2] = wt2;
        }
    }
}

// ---------------------------------------------------------------------------
// Kernel 2: expert-grouped MoE GEMM on tf32 mma.sync.
// ---------------------------------------------------------------------------
#define MOE_SMEM ((128*68 + 64*132 + 64*132 + 64*68) * 4)   // 119808 B

__global__ void __launch_bounds__(256) moe_gemm_kernel(
    const float* __restrict__ x,
    const float* __restrict__ qw1, const float* __restrict__ qw2,
    const float* __restrict__ kw1, const float* __restrict__ kw2,
    const float* __restrict__ vw1, const float* __restrict__ vw2)
{
    const int gid  = blockIdx.x;
    const int unit = gid / SPLITS;
    const int s    = gid % SPLITS;
    const int proj = unit >> 7;
    const int h    = (unit >> 3) & 15;
    const int e    = unit & 7;

    const float* w1 = ((proj == 0) ? qw1 : (proj == 1) ? kw1 : vw1) + (size_t)e * DD * HID;
    const float* w2 = ((proj == 0) ? qw2 : (proj == 1) ? kw2 : vw2) + (size_t)e * HID * DD;

    extern __shared__ uint smu[];
    uint* w1t = smu;                    // [128][68]  w1t[f*68 + d]
    uint* w2t = smu + 128*68;           // [64][132]  w2t[d*132 + j]
    uint* hsm = w2t + 64*132;           // [64][132]
    uint* xsm = hsm + 64*132;           // [64][68]
    __shared__ unsigned int stk[64];
    __shared__ float        swt[64];

    const int tid  = threadIdx.x;
    const int w    = tid >> 5;
    const int lane = tid & 31;
    const int g    = lane >> 2;
    const int tg   = lane & 3;
    const int wm   = w & 3;
    const int wn   = w >> 2;

    for (int i = tid; i < DD*HID; i += 256) {
        int d = i >> 7, f = i & 127;
        w1t[f*68 + d] = f2tf(w1[i]);
    }
    for (int i = tid; i < HID*DD; i += 256) {
        int j = i >> 6, d = i & 63;
        w2t[d*132 + j] = f2tf(w2[i]);
    }

    const int nt = (int)g_cnt[unit];
    const size_t ent_base = (size_t)unit * NTOK;

    for (int tile = s; tile * 64 < nt; tile += SPLITS) {
        const int base = tile * 64;
        __syncthreads();
        if (tid < 64) {
            int idx = base + tid;
            if (idx < nt) {
                stk[tid] = g_ent_id[ent_base + idx];
                swt[tid] = g_ent_wt[ent_base + idx];
            } else {
                stk[tid] = 0xFFFFFFFFu;
                swt[tid] = 0.0f;
            }
        }
        __syncthreads();
        {
            int tok = tid >> 2, part = tid & 3;
            unsigned int id = stk[tok];
            if (id != 0xFFFFFFFFu) {
                unsigned int tkk = id & 0x7FFFFFFFu;
                const float* src = x + (size_t)tkk * CC + h * DD + part * 16;
                uint* dst = xsm + tok * 68 + part * 16;
                #pragma unroll
                for (int q = 0; q < 16; q++) dst[q] = f2tf(src[q]);
            }
        }
        __syncthreads();

        // ---- stage 1: H = gelu(X @ W1) ----
        float c1[8][4];
        #pragma unroll
        for (int j = 0; j < 8; j++)
            #pragma unroll
            for (int r = 0; r < 4; r++) c1[j][r] = 0.0f;

        #pragma unroll
        for (int c = 0; c < 8; c++) {
            uint a[4];
            a[0] = xsm[(16*wm + g)    *68 + 8*c + tg];
            a[1] = xsm[(16*wm + g + 8)*68 + 8*c + tg];
            a[2] = xsm[(16*wm + g)    *68 + 8*c + tg + 4];
            a[3] = xsm[(16*wm + g + 8)*68 + 8*c + tg + 4];
            #pragma unroll
            for (int j = 0; j < 8; j++) {
                uint b0 = w1t[(64*wn + 8*j + g)*68 + 8*c + tg];
                uint b1 = w1t[(64*wn + 8*j + g)*68 + 8*c + tg + 4];
                mma_tf32(c1[j], a, b0, b1);
            }
        }
        #pragma unroll
        for (int j = 0; j < 8; j++) {
            int col = 64*wn + 8*j + 2*tg;
            hsm[(16*wm + g)    *132 + col]     = f2tf(gelu_tanh(c1[j][0]));
            hsm[(16*wm + g)    *132 + col + 1] = f2tf(gelu_tanh(c1[j][1]));
            hsm[(16*wm + g + 8)*132 + col]     = f2tf(gelu_tanh(c1[j][2]));
            hsm[(16*wm + g + 8)*132 + col + 1] = f2tf(gelu_tanh(c1[j][3]));
        }
        __syncthreads();

        // ---- stage 2: O = H @ W2 ----
        float c2[4][4];
        #pragma unroll
        for (int j = 0; j < 4; j++)
            #pragma unroll
            for (int r = 0; r < 4; r++) c2[j][r] = 0.0f;

        #pragma unroll
        for (int c = 0; c < 16; c++) {
            uint a[4];
            a[0] = hsm[(16*wm + g)    *132 + 8*c + tg];
            a[1] = hsm[(16*wm + g + 8)*132 + 8*c + tg];
            a[2] = hsm[(16*wm + g)    *132 + 8*c + tg + 4];
            a[3] = hsm[(16*wm + g + 8)*132 + 8*c + tg + 4];
            #pragma unroll
            for (int j = 0; j < 4; j++) {
                uint b0 = w2t[(32*wn + 8*j + g)*132 + 8*c + tg];
                uint b1 = w2t[(32*wn + 8*j + g)*132 + 8*c + tg + 4];
                mma_tf32(c2[j], a, b0, b1);
            }
        }

        int tokA = 16*wm + g, tokB = tokA + 8;
        unsigned int idA = stk[tokA], idB = stk[tokB];
        if (idA != 0xFFFFFFFFu) {
            float wt = swt[tokA];
            unsigned int slot = idA >> 31, tkk = idA & 0x7FFFFFFFu;
            float* dst = g_part + ((((size_t)slot*3 + proj)*HH + h)*NTOK + tkk)*DD;
            #pragma unroll
            for (int j = 0; j < 4; j++)
                *(float2*)&dst[32*wn + 8*j + 2*tg] =
                    make_float2(wt*c2[j][0], wt*c2[j][1]);
        }
        if (idB != 0xFFFFFFFFu) {
            float wt = swt[tokB];
            unsigned int slot = idB >> 31, tkk = idB & 0x7FFFFFFFu;
            float* dst = g_part + ((((size_t)slot*3 + proj)*HH + h)*NTOK + tkk)*DD;
            #pragma unroll
            for (int j = 0; j < 4; j++)
                *(float2*)&dst[32*wn + 8*j + 2*tg] =
                    make_float2(wt*c2[j][2], wt*c2[j][3]);
        }
    }
}

// ---------------------------------------------------------------------------
// Kernel 3: combine slots + RoPE; emits tf32-rounded values (Q pre-scaled).
// ---------------------------------------------------------------------------
__global__ void __launch_bounds__(256) combine_rope_kernel(
    const int* __restrict__ pos_ids,
    const float* __restrict__ cosT, const float* __restrict__ sinT)
{
    const int gw   = blockIdx.x * 8 + (threadIdx.x >> 5);
    const int lane = threadIdx.x & 31;
    const int proj = gw / (HH * NTOK);
    const int rest = gw % (HH * NTOK);
    const int h  = rest / NTOK;
    const int tk = rest % NTOK;

    const size_t SLOT = (size_t)3 * HH * NTOK * DD;
    const size_t pbase = (((size_t)proj * HH + h) * NTOK + tk) * DD;
    float a0 = g_part[pbase + lane]      + g_part[pbase + SLOT + lane];
    float a1 = g_part[pbase + lane + 32] + g_part[pbase + SLOT + lane + 32];

    if (proj < 2) {
        int p = pos_ids[tk];
        float c0 = cosT[p*DD + lane],  c1 = cosT[p*DD + lane + 32];
        float s0 = sinT[p*DD + lane],  s1 = sinT[p*DD + lane + 32];
        float r0 = a0 * c0 - a1 * s0;
        float r1 = a1 * c1 + a0 * s1;
        a0 = r0; a1 = r1;
    }
    if (proj == 0) { a0 *= 0.125f; a1 *= 0.125f; }

    int b = tk >> 10, t = tk & 1023;
    float* outg = (proj == 0) ? g_q : (proj == 1) ? g_k : g_v;
    size_t obase = (((size_t)b * HH + h) * TT + t) * DD;
    outg[obase + lane]      = __uint_as_float(f2tf(a0));
    outg[obase + lane + 32] = __uint_as_float(f2tf(a1));
}

// ---------------------------------------------------------------------------
// Kernel 4: causal flash attention, tf32 mma, BQ=128, BK=64, 256 threads.
// cp.async double-buffered K/V (inputs are pre-converted tf32 bits).
// smem words: K 2x4352, V 2x4608, psm/Qstage 8704  -> 26624 w = 106496 B
// ---------------------------------------------------------------------------
#define ATTN_SMEM (26624 * 4)

__global__ void __launch_bounds__(256, 2) attn_kernel()
{
    extern __shared__ uint smu[];
    uint* psm = smu + 17920;          // [8 warps][16 rows][68]

    const int qtb = 7 - blockIdx.x;   // heavy blocks first
    const int bh  = blockIdx.y;
    const int tid  = threadIdx.x;
    const int w    = tid >> 5;
    const int lane = tid & 31;
    const int g    = lane >> 2;
    const int tg   = lane & 3;
    uint* pw = psm + w * 1088;

    const float* qg = g_q + (size_t)bh * TT * DD;
    const float* kg = g_k + (size_t)bh * TT * DD;
    const float* vg = g_v + (size_t)bh * TT * DD;
    const int q0 = qtb * 128;
    const uint sbase = (uint)__cvta_generic_to_shared(smu);

    // stage Q (raw tf32 bits, pre-scaled) into psm, rows 0..127
    #pragma unroll
    for (int it = 0; it < 8; it++) {
        int idx = tid + it * 256;
        int row = idx >> 4, dc = (idx & 15) * 4;
        *(uint4*)&psm[row*68 + dc] = *(const uint4*)&qg[(size_t)(q0 + row)*DD + dc];
    }
    __syncthreads();
    uint qa[8][4];
    {
        int rA = 16*w + g;
        #pragma unroll
        for (int c = 0; c < 8; c++) {
            qa[c][0] = psm[rA*68     + 8*c + tg];
            qa[c][1] = psm[(rA+8)*68 + 8*c + tg];
            qa[c][2] = psm[rA*68     + 8*c + tg + 4];
            qa[c][3] = psm[(rA+8)*68 + 8*c + tg + 4];
        }
    }

    float oa[8][4];
    #pragma unroll
    for (int j = 0; j < 8; j++)
        #pragma unroll
        for (int r = 0; r < 4; r++) oa[j][r] = 0.0f;
    float mA = -1e30f, mB = -1e30f, lA = 0.0f, lB = 0.0f;

    const int ktmax = 2*qtb + 1;

    // issue tile kt into buffer kt&1
    #define ISSUE_TILE(kt_) do {                                              \
        int k0_ = (kt_) * 64;                                                 \
        uint kb_ = sbase + (((kt_) & 1) * 4352) * 4;                          \
        uint vb_ = sbase + (8704 + ((kt_) & 1) * 4608) * 4;                   \
        _Pragma("unroll")                                                     \
        for (int it_ = 0; it_ < 4; it_++) {                                   \
            int idx_ = tid + it_ * 256;                                       \
            int row_ = idx_ >> 4, dc_ = (idx_ & 15) * 4;                      \
            cpa16(kb_ + (row_*68 + dc_)*4, &kg[(size_t)(k0_ + row_)*DD + dc_]);\
            cpa16(vb_ + (row_*72 + dc_)*4, &vg[(size_t)(k0_ + row_)*DD + dc_]);\
        }                                                                     \
        asm volatile("cp.async.commit_group;");                               \
    } while (0)

    ISSUE_TILE(0);

    for (int kt = 0; kt <= ktmax; kt++) {
        if (kt < ktmax) {
            ISSUE_TILE(kt + 1);
            asm volatile("cp.async.wait_group 1;");
        } else {
            asm volatile("cp.async.wait_group 0;");
        }
        __syncthreads();
        const uint* ksm = smu + (kt & 1) * 4352;
        const uint* vsm = smu + 8704 + (kt & 1) * 4608;
        const int k0 = kt * 64;

        float sc[8][4];
        #pragma unroll
        for (int j = 0; j < 8; j++)
            #pragma unroll
            for (int r = 0; r < 4; r++) sc[j][r] = 0.0f;

        #pragma unroll
        for (int c = 0; c < 8; c++) {
            #pragma unroll
            for (int j = 0; j < 8; j++) {
                uint b0 = ksm[(8*j + g)*68 + 8*c + tg];
                uint b1 = ksm[(8*j + g)*68 + 8*c + tg + 4];
                mma_tf32(sc[j], qa[c], b0, b1);
            }
        }

        if (kt >= ktmax - 1) {
            const int rA = q0 + 16*w + g, rB = rA + 8;
            #pragma unroll
            for (int j = 0; j < 8; j++) {
                int col = k0 + 8*j + 2*tg;
                if (col     > rA) sc[j][0] = -1e30f;
                if (col + 1 > rA) sc[j][1] = -1e30f;
                if (col     > rB) sc[j][2] = -1e30f;
                if (col + 1 > rB) sc[j][3] = -1e30f;
            }
        }

        float mtA = -1e30f, mtB = -1e30f;
        #pragma unroll
        for (int j = 0; j < 8; j++) {
            mtA = fmaxf(mtA, fmaxf(sc[j][0], sc[j][1]));
            mtB = fmaxf(mtB, fmaxf(sc[j][2], sc[j][3]));
        }
        mtA = fmaxf(mtA, __shfl_xor_sync(0xffffffffu, mtA, 1));
        mtA = fmaxf(mtA, __shfl_xor_sync(0xffffffffu, mtA, 2));
        mtB = fmaxf(mtB, __shfl_xor_sync(0xffffffffu, mtB, 1));
        mtB = fmaxf(mtB, __shfl_xor_sync(0xffffffffu, mtB, 2));

        float mnA = fmaxf(mA, mtA), mnB = fmaxf(mB, mtB);
        float aA = __expf(mA - mnA), aB = __expf(mB - mnB);
        mA = mnA; mB = mnB;

        float psA = 0.0f, psB = 0.0f;
        #pragma unroll
        for (int j = 0; j < 8; j++) {
            sc[j][0] = __expf(sc[j][0] - mnA);
            sc[j][1] = __expf(sc[j][1] - mnA);
            sc[j][2] = __expf(sc[j][2] - mnB);
            sc[j][3] = __expf(sc[j][3] - mnB);
            psA += sc[j][0] + sc[j][1];
            psB += sc[j][2] + sc[j][3];
        }
        psA += __shfl_xor_sync(0xffffffffu, psA, 1);
        psA += __shfl_xor_sync(0xffffffffu, psA, 2);
        psB += __shfl_xor_sync(0xffffffffu, psB, 1);
        psB += __shfl_xor_sync(0xffffffffu, psB, 2);
        lA = lA * aA + psA;
        lB = lB * aB + psB;

        #pragma unroll
        for (int j = 0; j < 8; j++) {
            oa[j][0] *= aA; oa[j][1] *= aA;
            oa[j][2] *= aB; oa[j][3] *= aB;
        }

        #pragma unroll
        for (int j = 0; j < 8; j++) {
            pw[g*68     + 8*j + 2*tg]     = f2tf(sc[j][0]);
            pw[g*68     + 8*j + 2*tg + 1] = f2tf(sc[j][1]);
            pw[(g+8)*68 + 8*j + 2*tg]     = f2tf(sc[j][2]);
            pw[(g+8)*68 + 8*j + 2*tg + 1] = f2tf(sc[j][3]);
        }
        __syncwarp();

        #pragma unroll
        for (int c = 0; c < 8; c++) {
            uint pa[4];
            pa[0] = pw[g*68     + 8*c + tg];
            pa[1] = pw[(g+8)*68 + 8*c + tg];
            pa[2] = pw[g*68     + 8*c + tg + 4];
            pa[3] = pw[(g+8)*68 + 8*c + tg + 4];
            #pragma unroll
            for (int jd = 0; jd < 8; jd++) {
                uint b0 = vsm[(8*c + tg)*72     + 8*jd + g];
                uint b1 = vsm[(8*c + tg + 4)*72 + 8*jd + g];
                mma_tf32(oa[jd], pa, b0, b1);
            }
        }
        __syncthreads();
    }
    #undef ISSUE_TILE

    const int b = bh / HH, h = bh % HH;
    float invA = 1.0f / lA, invB = 1.0f / lB;
    const int rA = q0 + 16*w + g, rB = rA + 8;
    #pragma unroll
    for (int jd = 0; jd < 8; jd++) {
        *(float2*)&g_ao[((size_t)(b * TT) + rA) * CC + h * DD + 8*jd + 2*tg] =
            make_float2(oa[jd][0] * invA, oa[jd][1] * invA);
        *(float2*)&g_ao[((size_t)(b * TT) + rB) * CC + h * DD + 8*jd + 2*tg] =
            make_float2(oa[jd][2] * invB, oa[jd][3] * invB);
    }
}

// ---------------------------------------------------------------------------
// Kernel 5: y = ao @ ow^T, tf32 mma, BM=128, BN=64, BK=32, register prefetch.
// ---------------------------------------------------------------------------
__global__ void __launch_bounds__(256) outproj_kernel(
    const float* __restrict__ ow, float* __restrict__ y)
{
    __shared__ uint as[128*36];
    __shared__ uint bs[64*36];

    const int tid  = threadIdx.x;
    const int w    = tid >> 5;
    const int lane = tid & 31;
    const int g    = lane >> 2;
    const int tg   = lane & 3;
    const int n0 = blockIdx.x * 64;
    const int m0 = blockIdx.y * 128;

    float acc[8][4];
    #pragma unroll
    for (int j = 0; j < 8; j++)
        #pragma unroll
        for (int r = 0; r < 4; r++) acc[j][r] = 0.0f;

    float4 pa[4], pb[2];
    #pragma unroll
    for (int it = 0; it < 4; it++) {
        int idx = tid + it * 256;
        int row = idx >> 3, c4 = (idx & 7) * 4;
        pa[it] = *(const float4*)&g_ao[(size_t)(m0 + row) * 1024 + c4];
    }
    #pragma unroll
    for (int it = 0; it < 2; it++) {
        int idx = tid + it * 256;
        int row = idx >> 3, c4 = (idx & 7) * 4;
        pb[it] = *(const float4*)&ow[(size_t)(n0 + row) * 1024 + c4];
    }

    for (int k0 = 0; k0 < 1024; k0 += 32) {
        __syncthreads();
        #pragma unroll
        for (int it = 0; it < 4; it++) {
            int idx = tid + it * 256;
            int row = idx >> 3, c4 = (idx & 7) * 4;
            uint* d = &as[row*36 + c4];
            d[0] = f2tf(pa[it].x); d[1] = f2tf(pa[it].y);
            d[2] = f2tf(pa[it].z); d[3] = f2tf(pa[it].w);
        }
        #pragma unroll
        for (int it = 0; it < 2; it++) {
            int idx = tid + it * 256;
            int row = idx >> 3, c4 = (idx & 7) * 4;
            uint* d = &bs[row*36 + c4];
            d[0] = f2tf(pb[it].x); d[1] = f2tf(pb[it].y);
            d[2] = f2tf(pb[it].z); d[3] = f2tf(pb[it].w);
        }
        if (k0 + 32 < 1024) {
            #pragma unroll
            for (int it = 0; it < 4; it++) {
                int idx = tid + it * 256;
                int row = idx >> 3, c4 = (idx & 7) * 4;
                pa[it] = *(const float4*)&g_ao[(size_t)(m0 + row) * 1024 + k0 + 32 + c4];
            }
            #pragma unroll
            for (int it = 0; it < 2; it++) {
                int idx = tid + it * 256;
                int row = idx >> 3, c4 = (idx & 7) * 4;
                pb[it] = *(const float4*)&ow[(size_t)(n0 + row) * 1024 + k0 + 32 + c4];
            }
        }
        __syncthreads();

        #pragma unroll
        for (int c = 0; c < 4; c++) {
            uint a[4];
            a[0] = as[(16*w + g)    *36 + 8*c + tg];
            a[1] = as[(16*w + g + 8)*36 + 8*c + tg];
            a[2] = as[(16*w + g)    *36 + 8*c + tg + 4];
            a[3] = as[(16*w + g + 8)*36 + 8*c + tg + 4];
            #pragma unroll
            for (int j = 0; j < 8; j++) {
                uint b0 = bs[(8*j + g)*36 + 8*c + tg];
                uint b1 = bs[(8*j + g)*36 + 8*c + tg + 4];
                mma_tf32(acc[j], a, b0, b1);
            }
        }
    }

    const int rA = m0 + 16*w + g, rB = rA + 8;
    #pragma unroll
    for (int j = 0; j < 8; j++) {
        *(float2*)&y[(size_t)rA * 1024 + n0 + 8*j + 2*tg] =
            make_float2(acc[j][0], acc[j][1]);
        *(float2*)&y[(size_t)rB * 1024 + n0 + 8*j + 2*tg] =
            make_float2(acc[j][2], acc[j][3]);
    }
}

// ---------------------------------------------------------------------------
extern "C" void kernel_launch(void* const* d_in, const int* in_sizes, int n_in,
                              void* d_out, int out_size)
{
    const float* x    = (const float*)d_in[0];
    const int*   pid  = (const int*)  d_in[1];
    const float* cosT = (const float*)d_in[2];
    const float* sinT = (const float*)d_in[3];
    const float* rq   = (const float*)d_in[4];
    const float* rk   = (const float*)d_in[5];
    const float* rv   = (const float*)d_in[6];
    const float* qw1  = (const float*)d_in[7];
    const float* qw2  = (const float*)d_in[8];
    const float* kw1  = (const float*)d_in[9];
    const float* kw2  = (const float*)d_in[10];
    const float* vw1  = (const float*)d_in[11];
    const float* vw2  = (const float*)d_in[12];
    const float* ow   = (const float*)d_in[13];
    float* y = (float*)d_out;

    cudaFuncSetAttribute(moe_gemm_kernel,
                         cudaFuncAttributeMaxDynamicSharedMemorySize, MOE_SMEM);
    cudaFuncSetAttribute(attn_kernel,
                         cudaFuncAttributeMaxDynamicSharedMemorySize, ATTN_SMEM);

    zero_cnt_kernel<<<1, 512>>>();
    route_kernel<<<NTOK, 96>>>(x, rq, rk, rv);
    moe_gemm_kernel<<<NUNIT * SPLITS, 256, MOE_SMEM>>>(x, qw1, qw2, kw1, kw2, vw1, vw2);
    combine_rope_kernel<<<(3 * HH * NTOK) / 8, 256>>>(pid, cosT, sinT);

    dim3 g2(8, BB * HH);
    attn_kernel<<<g2, 256, ATTN_SMEM>>>();

    dim3 g3(CC / 64, (BB * TT) / 128);
    outproj_kernel<<<g3, 256>>>(ow, y);
}